// round 2
// baseline (speedup 1.0000x reference)
#include <cuda_runtime.h>
#include <math.h>

// ---------------- problem constants ----------------
#define Bn     8
#define Ssz    512
#define DIMn   1024
#define Hn     16
#define DHn    64
#define INNERn 1024
#define MLPn   4096
#define En     8
#define Kn     2
#define LRn    77
#define CAPn   2
#define Dlay   2

static const long SZX = (long)Bn * Ssz * DIMn;           // 4,194,304
static const long SZSC = (long)Bn * Hn * Ssz * Ssz;      // 33,554,432
static const long SZH  = (long)Bn * Kn * Ssz * MLPn;     // 33,554,432

// arena offsets (floats)
static const long O_LNQ = 0;
static const long O_LNK = O_LNQ + SZX;
static const long O_LNV = O_LNK + SZX;
static const long O_Q   = O_LNV + SZX;
static const long O_K   = O_Q   + SZX;
static const long O_V   = O_K   + SZX;
static const long O_O   = O_V   + SZX;
static const long O_XN  = O_O   + SZX;
static const long O_SC  = O_XN  + SZX;
static const long O_H   = O_SC  + SZSC;
static const long O_RM  = O_H   + SZH;            // 8*1024
static const long O_LG  = O_RM  + 8192;           // 64
static const long O_NL  = O_LG  + 64;             // 64
static const long O_FW  = O_NL  + 64;             // 16
static const long O_FE  = O_FW  + 16;             // 16 ints
static const long ARENA_FLOATS = O_FE + 64;

__device__ __align__(16) float g_arena[ARENA_FLOATS];

// ---------------- reductions ----------------
__device__ __forceinline__ float warpSum(float v) {
    #pragma unroll
    for (int o = 16; o; o >>= 1) v += __shfl_xor_sync(0xffffffffu, v, o);
    return v;
}
__device__ __forceinline__ float warpMax(float v) {
    #pragma unroll
    for (int o = 16; o; o >>= 1) v = fmaxf(v, __shfl_xor_sync(0xffffffffu, v, o));
    return v;
}

// ---------------- threefry2x32 (JAX-exact) ----------------
__device__ __forceinline__ void tf2x32(unsigned k0, unsigned k1, unsigned x0, unsigned x1,
                                       unsigned& o0, unsigned& o1) {
    unsigned ks0 = k0, ks1 = k1, ks2 = k0 ^ k1 ^ 0x1BD11BDAu;
    unsigned ks[3] = {ks0, ks1, ks2};
    const int R0[4] = {13, 15, 26, 6};
    const int R1[4] = {17, 29, 16, 24};
    x0 += ks[0]; x1 += ks[1];
    #pragma unroll
    for (int i = 0; i < 5; i++) {
        #pragma unroll
        for (int r = 0; r < 4; r++) {
            int rot = (i & 1) ? R1[r] : R0[r];
            x0 += x1;
            x1 = (x1 << rot) | (x1 >> (32 - rot));
            x1 ^= x0;
        }
        x0 += ks[(i + 1) % 3];
        x1 += ks[(i + 2) % 3] + (unsigned)(i + 1);
    }
    o0 = x0; o1 = x1;
}

// ---------------- GEMM tile body: 64x64x16, 256 thr, 4x4 micro ----------------
template <bool TB>
__device__ __forceinline__ void mm_body(const float* __restrict__ A, const float* __restrict__ B,
                                        int lda, int ldb, int K, int m0, int n0,
                                        float (&acc)[4][4], float (*As)[64], float (*Bs)[64]) {
    int tid = threadIdx.x;
    int ar = tid >> 2;           // 0..63
    int ac = (tid & 3) << 2;     // 0,4,8,12
    int ty4 = (tid >> 4) << 2;   // 0..60
    int tx4 = (tid & 15) << 2;   // 0..60
    for (int k0 = 0; k0 < K; k0 += 16) {
        float4 a4 = *(const float4*)(A + (long)(m0 + ar) * lda + k0 + ac);
        As[ac + 0][ar] = a4.x; As[ac + 1][ar] = a4.y;
        As[ac + 2][ar] = a4.z; As[ac + 3][ar] = a4.w;
        if (TB) {
            float4 b4 = *(const float4*)(B + (long)(n0 + ar) * ldb + k0 + ac);
            Bs[ac + 0][ar] = b4.x; Bs[ac + 1][ar] = b4.y;
            Bs[ac + 2][ar] = b4.z; Bs[ac + 3][ar] = b4.w;
        } else {
            int rb = tid >> 4;          // 0..15
            int cb = (tid & 15) << 2;   // 0..60
            *(float4*)&Bs[rb][cb] = *(const float4*)(B + (long)(k0 + rb) * ldb + n0 + cb);
        }
        __syncthreads();
        #pragma unroll
        for (int kk = 0; kk < 16; kk++) {
            float4 av = *(const float4*)&As[kk][ty4];
            float4 bv = *(const float4*)&Bs[kk][tx4];
            float a0[4] = {av.x, av.y, av.z, av.w};
            float b0[4] = {bv.x, bv.y, bv.z, bv.w};
            #pragma unroll
            for (int i = 0; i < 4; i++)
                #pragma unroll
                for (int j = 0; j < 4; j++)
                    acc[i][j] += a0[i] * b0[j];
        }
        __syncthreads();
    }
}

// EPI: 0 = C = scale*acc ; 1 = C = C + acc + bias[col]
template <int EPI, bool TB>
__global__ __launch_bounds__(256) void gemm_k(const float* __restrict__ Ag, const float* __restrict__ Bg,
                                              float* __restrict__ Cg, const float* __restrict__ bias,
                                              int M, int N, int K, int lda, int ldb, int ldc,
                                              long sAb, long sAh, long sBb, long sBh,
                                              long sCb, long sCh, int HH, float scale) {
    __shared__ __align__(16) float As[16][64];
    __shared__ __align__(16) float Bs[16][64];
    int z = blockIdx.z;
    int zb = z / HH, zh = z - zb * HH;
    const float* A = Ag + zb * sAb + zh * sAh;
    const float* B = Bg + zb * sBb + zh * sBh;
    float* C = Cg + zb * sCb + zh * sCh;
    int m0 = blockIdx.y * 64, n0 = blockIdx.x * 64;
    float acc[4][4] = {};
    mm_body<TB>(A, B, lda, ldb, K, m0, n0, acc, As, Bs);
    int ty4 = (threadIdx.x >> 4) << 2;
    int tx4 = (threadIdx.x & 15) << 2;
    #pragma unroll
    for (int i = 0; i < 4; i++)
        #pragma unroll
        for (int j = 0; j < 4; j++) {
            int col = n0 + tx4 + j;
            long idx = (long)(m0 + ty4 + i) * ldc + col;
            if (EPI == 0) C[idx] = acc[i][j] * scale;
            else          C[idx] = C[idx] + acc[i][j] + bias[col];
        }
}

// ---------------- MoE GEMMs ----------------
__global__ __launch_bounds__(256) void moe1_k(const float* __restrict__ xn, const float* __restrict__ W1l,
                                              const float* __restrict__ b1l, float* __restrict__ Hout,
                                              const int* __restrict__ fe, const float* __restrict__ fw) {
    int n = blockIdx.z;
    if (fw[n] == 0.0f) return;
    int e = fe[n];
    const float* A = xn + (long)(n >> 1) * Ssz * DIMn;
    const float* B = W1l + (long)e * DIMn * MLPn;
    float* C = Hout + (long)n * Ssz * MLPn;
    const float* bias = b1l + (long)e * MLPn;
    __shared__ __align__(16) float As[16][64];
    __shared__ __align__(16) float Bs[16][64];
    int m0 = blockIdx.y * 64, n0 = blockIdx.x * 64;
    float acc[4][4] = {};
    mm_body<false>(A, B, DIMn, MLPn, DIMn, m0, n0, acc, As, Bs);
    int ty4 = (threadIdx.x >> 4) << 2;
    int tx4 = (threadIdx.x & 15) << 2;
    #pragma unroll
    for (int i = 0; i < 4; i++)
        #pragma unroll
        for (int j = 0; j < 4; j++) {
            int col = n0 + tx4 + j;
            float v = acc[i][j] + bias[col];
            C[(long)(m0 + ty4 + i) * MLPn + col] = 0.5f * v * (1.0f + erff(v * 0.70710678118654752f));
        }
}

__global__ __launch_bounds__(256) void moe2_k(const float* __restrict__ Hin, const float* __restrict__ W2l,
                                              const float* __restrict__ b2l, float* __restrict__ X,
                                              const int* __restrict__ fe, const float* __restrict__ fw) {
    int n = blockIdx.z;
    float w = fw[n];
    if (w == 0.0f) return;
    int e = fe[n];
    const float* A = Hin + (long)n * Ssz * MLPn;
    const float* B = W2l + (long)e * MLPn * DIMn;
    float* C = X + (long)(n >> 1) * Ssz * DIMn;
    const float* bias = b2l + (long)e * DIMn;
    __shared__ __align__(16) float As[16][64];
    __shared__ __align__(16) float Bs[16][64];
    int m0 = blockIdx.y * 64, n0 = blockIdx.x * 64;
    float acc[4][4] = {};
    mm_body<false>(A, B, MLPn, DIMn, MLPn, m0, n0, acc, As, Bs);
    int ty4 = (threadIdx.x >> 4) << 2;
    int tx4 = (threadIdx.x & 15) << 2;
    #pragma unroll
    for (int i = 0; i < 4; i++)
        #pragma unroll
        for (int j = 0; j < 4; j++) {
            int col = n0 + tx4 + j;
            atomicAdd(&C[(long)(m0 + ty4 + i) * DIMn + col], (acc[i][j] + bias[col]) * w);
        }
}

// ---------------- LayerNorm ----------------
__global__ __launch_bounds__(256) void ln3_k(const float* __restrict__ X,
                                             const float* __restrict__ wq, const float* __restrict__ bq,
                                             const float* __restrict__ wk, const float* __restrict__ bk,
                                             const float* __restrict__ wv, const float* __restrict__ bv,
                                             float* __restrict__ oq, float* __restrict__ ok,
                                             float* __restrict__ ov) {
    __shared__ float sh[8];
    long row = blockIdx.x;
    const float* xr = X + row * DIMn;
    int t = threadIdx.x;
    float v[4]; float s = 0.f;
    #pragma unroll
    for (int i = 0; i < 4; i++) { v[i] = xr[t + i * 256]; s += v[i]; }
    s = warpSum(s);
    if ((t & 31) == 0) sh[t >> 5] = s;
    __syncthreads();
    if (t < 32) { float a = (t < 8) ? sh[t] : 0.f; a = warpSum(a); if (t == 0) sh[0] = a; }
    __syncthreads();
    float mean = sh[0] * (1.0f / DIMn);
    __syncthreads();
    float ss = 0.f;
    #pragma unroll
    for (int i = 0; i < 4; i++) { float d = v[i] - mean; ss += d * d; }
    ss = warpSum(ss);
    if ((t & 31) == 0) sh[t >> 5] = ss;
    __syncthreads();
    if (t < 32) { float a = (t < 8) ? sh[t] : 0.f; a = warpSum(a); if (t == 0) sh[0] = a; }
    __syncthreads();
    float rstd = rsqrtf(sh[0] * (1.0f / DIMn) + 1e-5f);
    #pragma unroll
    for (int i = 0; i < 4; i++) {
        int c = t + i * 256;
        float xh = (v[i] - mean) * rstd;
        long idx = row * DIMn + c;
        oq[idx] = xh * wq[c] + bq[c];
        ok[idx] = xh * wk[c] + bk[c];
        ov[idx] = xh * wv[c] + bv[c];
    }
}

__global__ __launch_bounds__(256) void ln1_k(const float* __restrict__ X,
                                             const float* __restrict__ w, const float* __restrict__ b,
                                             float* __restrict__ out) {
    __shared__ float sh[8];
    long row = blockIdx.x;
    const float* xr = X + row * DIMn;
    int t = threadIdx.x;
    float v[4]; float s = 0.f;
    #pragma unroll
    for (int i = 0; i < 4; i++) { v[i] = xr[t + i * 256]; s += v[i]; }
    s = warpSum(s);
    if ((t & 31) == 0) sh[t >> 5] = s;
    __syncthreads();
    if (t < 32) { float a = (t < 8) ? sh[t] : 0.f; a = warpSum(a); if (t == 0) sh[0] = a; }
    __syncthreads();
    float mean = sh[0] * (1.0f / DIMn);
    __syncthreads();
    float ss = 0.f;
    #pragma unroll
    for (int i = 0; i < 4; i++) { float d = v[i] - mean; ss += d * d; }
    ss = warpSum(ss);
    if ((t & 31) == 0) sh[t >> 5] = ss;
    __syncthreads();
    if (t < 32) { float a = (t < 8) ? sh[t] : 0.f; a = warpSum(a); if (t == 0) sh[0] = a; }
    __syncthreads();
    float rstd = rsqrtf(sh[0] * (1.0f / DIMn) + 1e-5f);
    #pragma unroll
    for (int i = 0; i < 4; i++) {
        int c = t + i * 256;
        long idx = row * DIMn + c;
        out[idx] = (v[i] - mean) * rstd * w[c] + b[c];
    }
}

// ---------------- softmax over rows of 512 ----------------
__global__ __launch_bounds__(128) void softmax_k(float* __restrict__ S) {
    __shared__ float sh[4];
    long row = blockIdx.x;
    float* p = S + row * 512;
    int t = threadIdx.x;
    float v[4];
    #pragma unroll
    for (int i = 0; i < 4; i++) v[i] = p[t + i * 128];
    float m = fmaxf(fmaxf(v[0], v[1]), fmaxf(v[2], v[3]));
    m = warpMax(m);
    if ((t & 31) == 0) sh[t >> 5] = m;
    __syncthreads();
    if (t < 32) { float a = (t < 4) ? sh[t] : -INFINITY; a = warpMax(a); if (t == 0) sh[0] = a; }
    __syncthreads();
    m = sh[0];
    __syncthreads();
    float s = 0.f;
    #pragma unroll
    for (int i = 0; i < 4; i++) { v[i] = expf(v[i] - m); s += v[i]; }
    s = warpSum(s);
    if ((t & 31) == 0) sh[t >> 5] = s;
    __syncthreads();
    if (t < 32) { float a = (t < 4) ? sh[t] : 0.f; a = warpSum(a); if (t == 0) sh[0] = a; }
    __syncthreads();
    float inv = 1.0f / sh[0];
    #pragma unroll
    for (int i = 0; i < 4; i++) p[t + i * 128] = v[i] * inv;
}

// ---------------- router mean over LR ----------------
__global__ void rimean_k(const float* __restrict__ ri, float* __restrict__ rm) {
    int i = blockIdx.x * 256 + threadIdx.x;   // 8192 total
    int b = i >> 10, d = i & 1023;
    float s = 0.f;
    for (int r = 0; r < LRn; r++) s += ri[((long)b * LRn + r) * DIMn + d];
    rm[i] = s * (1.0f / LRn);
}

// ---------------- router logits ----------------
__global__ __launch_bounds__(256) void logits_k(const float* __restrict__ rm,
                                                const float* __restrict__ Wr, const float* __restrict__ br,
                                                const float* __restrict__ Wn, const float* __restrict__ bn,
                                                float* __restrict__ lg, float* __restrict__ nl) {
    __shared__ float sh[16];
    int b = blockIdx.x >> 3, e = blockIdx.x & 7;
    int t = threadIdx.x;
    float s1 = 0.f, s2 = 0.f;
    for (int d = t; d < DIMn; d += 256) {
        float r = rm[b * DIMn + d];
        s1 += r * Wr[(long)d * En + e];
        s2 += r * Wn[(long)d * En + e];
    }
    s1 = warpSum(s1); s2 = warpSum(s2);
    if ((t & 31) == 0) { sh[t >> 5] = s1; sh[8 + (t >> 5)] = s2; }
    __syncthreads();
    if (t == 0) {
        float a = 0.f, c = 0.f;
        for (int i = 0; i < 8; i++) { a += sh[i]; c += sh[8 + i]; }
        lg[blockIdx.x] = a + br[e];
        nl[blockIdx.x] = c + bn[e];
    }
}

// ---------------- noisy top-k routing + capacity ----------------
// JAX threefry with jax_threefry_partitionable=True (modern default):
// bits[i] = o0 ^ o1 where (o0, o1) = threefry2x32(key, (hi=0, lo=i))
__global__ void route_k(const float* __restrict__ logits, const float* __restrict__ nlog, int l,
                        int* __restrict__ fe, float* __restrict__ fw) {
    __shared__ float sc[64];
    __shared__ int se[16];
    __shared__ float sg[16];
    int t = threadIdx.x;
    if (t < 64) {
        unsigned kk0, kk1;
        tf2x32(0u, 42u, 0u, (unsigned)l, kk0, kk1);       // fold_in(key(42), l)
        unsigned o0, o1;
        tf2x32(kk0, kk1, 0u, (unsigned)t, o0, o1);        // partitionable counter mode
        unsigned bits = o0 ^ o1;
        float f = __uint_as_float(0x3f800000u | (bits >> 9)) - 1.0f;
        const float lo = -0.99999994f;                    // nextafter(-1, 0) fp32
        float u = f * 2.0f + lo;                          // (hi-lo) rounds to exactly 2.0f
        u = fmaxf(lo, u);
        float g = 1.41421356237309515f * erfinvf(u);
        float xnl = nlog[t];
        float sp = fmaxf(xnl, 0.f) + log1pf(expf(-fabsf(xnl)));  // softplus, logaddexp form
        sc[t] = logits[t] + g * sp;
    }
    __syncthreads();
    if (t < 8) {
        const float* row = sc + t * 8;
        int e0 = 0; float v0 = row[0];
        for (int e = 1; e < 8; e++) if (row[e] > v0) { v0 = row[e]; e0 = e; }
        int e1 = -1; float v1 = -INFINITY;
        for (int e = 0; e < 8; e++) if (e != e0 && row[e] > v1) { v1 = row[e]; e1 = e; }
        float d = expf(v1 - v0);
        float inv = 1.0f / (1.0f + d);
        se[t * 2] = e0; se[t * 2 + 1] = e1;
        sg[t * 2] = inv; sg[t * 2 + 1] = d * inv;
    }
    __syncthreads();
    if (t == 0) {
        int cnt[8] = {0, 0, 0, 0, 0, 0, 0, 0};
        for (int n = 0; n < 16; n++) {
            int e = se[n];
            float w = (cnt[e] < CAPn) ? sg[n] : 0.0f;
            cnt[e]++;
            fe[n] = e; fw[n] = w;
        }
    }
}

// ---------------- host launch ----------------
extern "C" void kernel_launch(void* const* d_in, const int* in_sizes, int n_in,
                              void* d_out, int out_size) {
    (void)in_sizes; (void)n_in; (void)out_size;
    const float* router_input = (const float*)d_in[0];
    const float* x0   = (const float*)d_in[1];
    const float* nq_w = (const float*)d_in[2];
    const float* nq_b = (const float*)d_in[3];
    const float* nk_w = (const float*)d_in[4];
    const float* nk_b = (const float*)d_in[5];
    const float* nv_w = (const float*)d_in[6];
    const float* nv_b = (const float*)d_in[7];
    const float* Wq   = (const float*)d_in[8];
    const float* Wk   = (const float*)d_in[9];
    const float* Wv   = (const float*)d_in[10];
    const float* Wo   = (const float*)d_in[11];
    const float* bo   = (const float*)d_in[12];
    const float* nm_w = (const float*)d_in[13];
    const float* nm_b = (const float*)d_in[14];
    const float* Wr   = (const float*)d_in[15];
    const float* br   = (const float*)d_in[16];
    const float* Wn   = (const float*)d_in[17];
    const float* bn   = (const float*)d_in[18];
    const float* W1   = (const float*)d_in[19];
    const float* b1   = (const float*)d_in[20];
    const float* W2   = (const float*)d_in[21];
    const float* b2   = (const float*)d_in[22];

    float* X = (float*)d_out;
    float* arena = nullptr;
    cudaGetSymbolAddress((void**)&arena, g_arena);
    float* lnq = arena + O_LNQ;
    float* lnk = arena + O_LNK;
    float* lnv = arena + O_LNV;
    float* qb  = arena + O_Q;
    float* kb  = arena + O_K;
    float* vb  = arena + O_V;
    float* ob  = arena + O_O;
    float* xn  = arena + O_XN;
    float* sc  = arena + O_SC;
    float* hb  = arena + O_H;
    float* rm  = arena + O_RM;
    float* lg  = arena + O_LG;
    float* nl  = arena + O_NL;
    float* fw  = arena + O_FW;
    int*   fe  = (int*)(arena + O_FE);

    cudaMemcpyAsync(X, x0, sizeof(float) * SZX, cudaMemcpyDeviceToDevice);
    rimean_k<<<32, 256>>>(router_input, rm);

    const long sQb = (long)Ssz * INNERn;   // per-batch stride in q/k/v/o
    const long sQh = DHn;                  // per-head stride
    const long sScb = (long)Hn * Ssz * Ssz;
    const long sSch = (long)Ssz * Ssz;

    for (int l = 0; l < Dlay; l++) {
        const float* Wq_l = Wq + (long)l * DIMn * INNERn;
        const float* Wk_l = Wk + (long)l * DIMn * INNERn;
        const float* Wv_l = Wv + (long)l * DIMn * INNERn;
        const float* Wo_l = Wo + (long)l * INNERn * DIMn;

        ln3_k<<<Bn * Ssz, 256>>>(X, nq_w + l * DIMn, nq_b + l * DIMn,
                                 nk_w + l * DIMn, nk_b + l * DIMn,
                                 nv_w + l * DIMn, nv_b + l * DIMn, lnq, lnk, lnv);

        gemm_k<0, false><<<dim3(INNERn / 64, Bn * Ssz / 64, 1), 256>>>(
            lnq, Wq_l, qb, nullptr, Bn * Ssz, INNERn, DIMn, DIMn, INNERn, INNERn,
            0, 0, 0, 0, 0, 0, 1, 1.0f);
        gemm_k<0, false><<<dim3(INNERn / 64, Bn * Ssz / 64, 1), 256>>>(
            lnk, Wk_l, kb, nullptr, Bn * Ssz, INNERn, DIMn, DIMn, INNERn, INNERn,
            0, 0, 0, 0, 0, 0, 1, 1.0f);
        gemm_k<0, false><<<dim3(INNERn / 64, Bn * Ssz / 64, 1), 256>>>(
            lnv, Wv_l, vb, nullptr, Bn * Ssz, INNERn, DIMn, DIMn, INNERn, INNERn,
            0, 0, 0, 0, 0, 0, 1, 1.0f);

        // scores = Q K^T * scale  (batched over B*H)
        gemm_k<0, true><<<dim3(Ssz / 64, Ssz / 64, Bn * Hn), 256>>>(
            qb, kb, sc, nullptr, Ssz, Ssz, DHn, INNERn, INNERn, Ssz,
            sQb, sQh, sQb, sQh, sScb, sSch, Hn, 0.125f);

        softmax_k<<<Bn * Hn * Ssz, 128>>>(sc);

        // O = P V
        gemm_k<0, false><<<dim3(1, Ssz / 64, Bn * Hn), 256>>>(
            sc, vb, ob, nullptr, Ssz, DHn, Ssz, Ssz, INNERn, INNERn,
            sScb, sSch, sQb, sQh, sQb, sQh, Hn, 1.0f);

        // X += O @ Wo + bo
        gemm_k<1, false><<<dim3(DIMn / 64, Bn * Ssz / 64, 1), 256>>>(
            ob, Wo_l, X, bo + l * DIMn, Bn * Ssz, DIMn, INNERn, INNERn, DIMn, DIMn,
            0, 0, 0, 0, 0, 0, 1, 1.0f);

        // routing
        logits_k<<<Bn * En, 256>>>(rm, Wr + (long)l * DIMn * En, br + l * En,
                                   Wn + (long)l * DIMn * En, bn + l * En, lg, nl);
        route_k<<<1, 64>>>(lg, nl, l, fe, fw);

        // MoE
        ln1_k<<<Bn * Ssz, 256>>>(X, nm_w + l * DIMn, nm_b + l * DIMn, xn);
        moe1_k<<<dim3(MLPn / 64, Ssz / 64, Bn * Kn), 256>>>(
            xn, W1 + (long)l * En * DIMn * MLPn, b1 + (long)l * En * MLPn, hb, fe, fw);
        moe2_k<<<dim3(DIMn / 64, Ssz / 64, Bn * Kn), 256>>>(
            hb, W2 + (long)l * En * MLPn * DIMn, b2 + (long)l * En * DIMn, X, fe, fw);
    }
}

// round 3
// speedup vs baseline: 1.4335x; 1.4335x over previous
#include <cuda_runtime.h>
#include <math.h>
#include <mma.h>

using namespace nvcuda;

// ---------------- problem constants ----------------
#define Bn     8
#define Ssz    512
#define DIMn   1024
#define Hn     16
#define DHn    64
#define INNERn 1024
#define MLPn   4096
#define En     8
#define Kn     2
#define LRn    77
#define CAPn   2
#define Dlay   2

static const long SZX = (long)Bn * Ssz * DIMn;           // 4,194,304
static const long SZSC = (long)Bn * Hn * Ssz * Ssz;      // 33,554,432
static const long SZH  = (long)Bn * Kn * Ssz * MLPn;     // 33,554,432

// arena offsets (floats)
static const long O_LNQ = 0;
static const long O_LNK = O_LNQ + SZX;
static const long O_LNV = O_LNK + SZX;
static const long O_Q   = O_LNV + SZX;
static const long O_K   = O_Q   + SZX;
static const long O_V   = O_K   + SZX;
static const long O_O   = O_V   + SZX;
static const long O_XN  = O_O   + SZX;
static const long O_SC  = O_XN  + SZX;
static const long O_H   = O_SC  + SZSC;
static const long O_RM  = O_H   + SZH;            // 8*1024
static const long O_LG  = O_RM  + 8192;           // 64
static const long O_NL  = O_LG  + 64;             // 64
static const long O_FW  = O_NL  + 64;             // 16
static const long O_FE  = O_FW  + 16;             // 16 ints
static const long ARENA_FLOATS = O_FE + 64;

__device__ __align__(16) float g_arena[ARENA_FLOATS];

// ---------------- reductions ----------------
__device__ __forceinline__ float warpSum(float v) {
    #pragma unroll
    for (int o = 16; o; o >>= 1) v += __shfl_xor_sync(0xffffffffu, v, o);
    return v;
}
__device__ __forceinline__ float warpMax(float v) {
    #pragma unroll
    for (int o = 16; o; o >>= 1) v = fmaxf(v, __shfl_xor_sync(0xffffffffu, v, o));
    return v;
}

// ---------------- threefry2x32 (JAX-exact) ----------------
__device__ __forceinline__ void tf2x32(unsigned k0, unsigned k1, unsigned x0, unsigned x1,
                                       unsigned& o0, unsigned& o1) {
    unsigned ks0 = k0, ks1 = k1, ks2 = k0 ^ k1 ^ 0x1BD11BDAu;
    unsigned ks[3] = {ks0, ks1, ks2};
    const int R0[4] = {13, 15, 26, 6};
    const int R1[4] = {17, 29, 16, 24};
    x0 += ks[0]; x1 += ks[1];
    #pragma unroll
    for (int i = 0; i < 5; i++) {
        #pragma unroll
        for (int r = 0; r < 4; r++) {
            int rot = (i & 1) ? R1[r] : R0[r];
            x0 += x1;
            x1 = (x1 << rot) | (x1 >> (32 - rot));
            x1 ^= x0;
        }
        x0 += ks[(i + 1) % 3];
        x1 += ks[(i + 2) % 3] + (unsigned)(i + 1);
    }
    o0 = x0; o1 = x1;
}

// =================================================================
// WMMA tf32 GEMM: 128x128 CTA tile, BK=32, 8 warps (4Mx2N), warp=32x64
// =================================================================
using FragA = wmma::fragment<wmma::matrix_a, 16, 16, 8, wmma::precision::tf32, wmma::row_major>;
using FragB = wmma::fragment<wmma::matrix_b, 16, 16, 8, wmma::precision::tf32, wmma::row_major>;
using FragC = wmma::fragment<wmma::accumulator, 16, 16, 8, float>;

__device__ __forceinline__ float tf32r(float x) { return wmma::__float_to_tf32(x); }

// mainloop: A row-major [M,K] lda, B row-major [K,N] ldb; K multiple of 32,
// tile fully in-bounds (all our shapes are multiples of 128/32).
__device__ __forceinline__ void wmm_main(const float* __restrict__ A, const float* __restrict__ B,
                                         int lda, int ldb, int K, int m0, int n0,
                                         float (&sA)[128][36], float (&sB)[32][132],
                                         FragC (&acc)[2][4]) {
    int tid = threadIdx.x;
    int warp = tid >> 5;
    int wm = warp & 3, wn = warp >> 2;
    int arow = tid >> 1, ac4 = (tid & 1) * 4;   // A: 2 threads/row, 16 cols each
    int brow = tid >> 3, bc4 = (tid & 7) * 4;   // B: 8 threads/row, 16 cols each
    const float* Abase = A + (long)(m0 + arow) * lda + ac4 * 4;
    const float* Bbase = B + n0 + bc4 * 4;

    float4 ra[4], rb[4];
    #pragma unroll
    for (int i = 0; i < 4; i++) ra[i] = *(const float4*)(Abase + i * 4);
    #pragma unroll
    for (int i = 0; i < 4; i++) rb[i] = *(const float4*)(Bbase + (long)brow * ldb + i * 4);

    #pragma unroll 1
    for (int k0 = 32; ; k0 += 32) {
        // stage regs -> smem (tf32 round-to-nearest once per element)
        #pragma unroll
        for (int i = 0; i < 4; i++) {
            float* p = &sA[arow][(ac4 + i) * 4];
            p[0] = tf32r(ra[i].x); p[1] = tf32r(ra[i].y);
            p[2] = tf32r(ra[i].z); p[3] = tf32r(ra[i].w);
            float* q = &sB[brow][(bc4 + i) * 4];
            q[0] = tf32r(rb[i].x); q[1] = tf32r(rb[i].y);
            q[2] = tf32r(rb[i].z); q[3] = tf32r(rb[i].w);
        }
        __syncthreads();

        bool nxt = k0 < K;
        if (nxt) {
            #pragma unroll
            for (int i = 0; i < 4; i++) ra[i] = *(const float4*)(Abase + k0 + i * 4);
            #pragma unroll
            for (int i = 0; i < 4; i++) rb[i] = *(const float4*)(Bbase + (long)(k0 + brow) * ldb + i * 4);
        }

        #pragma unroll
        for (int kk = 0; kk < 4; kk++) {
            FragA af[2];
            FragB bf[4];
            #pragma unroll
            for (int i = 0; i < 2; i++)
                wmma::load_matrix_sync(af[i], &sA[wm * 32 + i * 16][kk * 8], 36);
            #pragma unroll
            for (int j = 0; j < 4; j++)
                wmma::load_matrix_sync(bf[j], &sB[kk * 8][wn * 64 + j * 16], 132);
            #pragma unroll
            for (int i = 0; i < 2; i++)
                #pragma unroll
                for (int j = 0; j < 4; j++)
                    wmma::mma_sync(acc[i][j], af[i], bf[j], acc[i][j]);
        }
        if (!nxt) break;
        __syncthreads();
    }
}

// EPI: 1 = C += acc + bias ; 2 = C = gelu(acc + bias) ; 3 = atomicAdd(C, (acc+bias)*w)
template <int EPI>
__device__ __forceinline__ void wepilogue(FragC (&acc)[2][4], float* stage_w,
                                          float* __restrict__ C, const float* __restrict__ bias,
                                          int ldc, int m0, int n0, float w) {
    int tid = threadIdx.x, warp = tid >> 5, lane = tid & 31;
    int wm = warp & 3, wn = warp >> 2;
    int r = lane >> 1, cb = (lane & 1) * 8;
    #pragma unroll
    for (int i = 0; i < 2; i++)
        #pragma unroll
        for (int j = 0; j < 4; j++) {
            wmma::store_matrix_sync(stage_w, acc[i][j], 20, wmma::mem_row_major);
            __syncwarp();
            int row = m0 + wm * 32 + i * 16 + r;
            int col0 = n0 + wn * 64 + j * 16 + cb;
            #pragma unroll
            for (int c = 0; c < 8; c++) {
                float v = stage_w[r * 20 + cb + c];
                int col = col0 + c;
                long idx = (long)row * ldc + col;
                if (EPI == 1) C[idx] = C[idx] + v + bias[col];
                else if (EPI == 2) {
                    float u = v + bias[col];
                    C[idx] = 0.5f * u * (1.0f + erff(u * 0.70710678118654752f));
                } else {
                    atomicAdd(&C[idx], (v + bias[col]) * w);
                }
            }
            __syncwarp();
        }
}

// EPI 0: plain C = acc ; EPI 1: C += acc + bias
template <int EPI>
__global__ __launch_bounds__(256) void wgemm_k(const float* __restrict__ A, const float* __restrict__ B,
                                               float* __restrict__ C, const float* __restrict__ bias,
                                               int K, int lda, int ldb, int ldc) {
    __shared__ float sA[128][36];
    __shared__ float sB[32][132];
    __shared__ float stage[8][320];
    int m0 = blockIdx.y * 128, n0 = blockIdx.x * 128;
    FragC acc[2][4];
    #pragma unroll
    for (int i = 0; i < 2; i++)
        #pragma unroll
        for (int j = 0; j < 4; j++) wmma::fill_fragment(acc[i][j], 0.0f);
    wmm_main(A, B, lda, ldb, K, m0, n0, sA, sB, acc);
    int warp = threadIdx.x >> 5;
    int wm = warp & 3, wn = warp >> 2;
    if (EPI == 0) {
        #pragma unroll
        for (int i = 0; i < 2; i++)
            #pragma unroll
            for (int j = 0; j < 4; j++)
                wmma::store_matrix_sync(&C[(long)(m0 + wm * 32 + i * 16) * ldc + n0 + wn * 64 + j * 16],
                                        acc[i][j], ldc, wmma::mem_row_major);
    } else {
        wepilogue<1>(acc, &stage[warp][0], C, bias, ldc, m0, n0, 0.0f);
    }
}

// MoE first GEMM: H = gelu(xn[slot] @ W1[e] + b1[e])
__global__ __launch_bounds__(256) void moe1_w(const float* __restrict__ xn, const float* __restrict__ W1l,
                                              const float* __restrict__ b1l, float* __restrict__ H,
                                              const int* __restrict__ fe, const float* __restrict__ fw) {
    int n = blockIdx.z;
    if (fw[n] == 0.0f) return;
    int e = fe[n];
    const float* A = xn + (long)(n >> 1) * Ssz * DIMn;
    const float* B = W1l + (long)e * DIMn * MLPn;
    float* C = H + (long)n * Ssz * MLPn;
    const float* bias = b1l + (long)e * MLPn;
    __shared__ float sA[128][36];
    __shared__ float sB[32][132];
    __shared__ float stage[8][320];
    int m0 = blockIdx.y * 128, n0 = blockIdx.x * 128;
    FragC acc[2][4];
    #pragma unroll
    for (int i = 0; i < 2; i++)
        #pragma unroll
        for (int j = 0; j < 4; j++) wmma::fill_fragment(acc[i][j], 0.0f);
    wmm_main(A, B, DIMn, MLPn, DIMn, m0, n0, sA, sB, acc);
    wepilogue<2>(acc, &stage[threadIdx.x >> 5][0], C, bias, MLPn, m0, n0, 0.0f);
}

// MoE second GEMM: X[slot>>1] += (H[slot] @ W2[e] + b2[e]) * w  (atomic combine)
__global__ __launch_bounds__(256) void moe2_w(const float* __restrict__ H, const float* __restrict__ W2l,
                                              const float* __restrict__ b2l, float* __restrict__ X,
                                              const int* __restrict__ fe, const float* __restrict__ fw) {
    int n = blockIdx.z;
    float w = fw[n];
    if (w == 0.0f) return;
    int e = fe[n];
    const float* A = H + (long)n * Ssz * MLPn;
    const float* B = W2l + (long)e * MLPn * DIMn;
    float* C = X + (long)(n >> 1) * Ssz * DIMn;
    const float* bias = b2l + (long)e * DIMn;
    __shared__ float sA[128][36];
    __shared__ float sB[32][132];
    __shared__ float stage[8][320];
    int m0 = blockIdx.y * 128, n0 = blockIdx.x * 128;
    FragC acc[2][4];
    #pragma unroll
    for (int i = 0; i < 2; i++)
        #pragma unroll
        for (int j = 0; j < 4; j++) wmma::fill_fragment(acc[i][j], 0.0f);
    wmm_main(A, B, MLPn, DIMn, MLPn, m0, n0, sA, sB, acc);
    wepilogue<3>(acc, &stage[threadIdx.x >> 5][0], C, bias, DIMn, m0, n0, w);
}

// ---------------- FFMA GEMM (attention only): 64x64x16 tile ----------------
template <bool TB>
__device__ __forceinline__ void mm_body(const float* __restrict__ A, const float* __restrict__ B,
                                        int lda, int ldb, int K, int m0, int n0,
                                        float (&acc)[4][4], float (*As)[64], float (*Bs)[64]) {
    int tid = threadIdx.x;
    int ar = tid >> 2;
    int ac = (tid & 3) << 2;
    int ty4 = (tid >> 4) << 2;
    int tx4 = (tid & 15) << 2;
    for (int k0 = 0; k0 < K; k0 += 16) {
        float4 a4 = *(const float4*)(A + (long)(m0 + ar) * lda + k0 + ac);
        As[ac + 0][ar] = a4.x; As[ac + 1][ar] = a4.y;
        As[ac + 2][ar] = a4.z; As[ac + 3][ar] = a4.w;
        if (TB) {
            float4 b4 = *(const float4*)(B + (long)(n0 + ar) * ldb + k0 + ac);
            Bs[ac + 0][ar] = b4.x; Bs[ac + 1][ar] = b4.y;
            Bs[ac + 2][ar] = b4.z; Bs[ac + 3][ar] = b4.w;
        } else {
            int rb = tid >> 4;
            int cb = (tid & 15) << 2;
            *(float4*)&Bs[rb][cb] = *(const float4*)(B + (long)(k0 + rb) * ldb + n0 + cb);
        }
        __syncthreads();
        #pragma unroll
        for (int kk = 0; kk < 16; kk++) {
            float4 av = *(const float4*)&As[kk][ty4];
            float4 bv = *(const float4*)&Bs[kk][tx4];
            float a0[4] = {av.x, av.y, av.z, av.w};
            float b0[4] = {bv.x, bv.y, bv.z, bv.w};
            #pragma unroll
            for (int i = 0; i < 4; i++)
                #pragma unroll
                for (int j = 0; j < 4; j++)
                    acc[i][j] += a0[i] * b0[j];
        }
        __syncthreads();
    }
}

template <int EPI, bool TB>
__global__ __launch_bounds__(256) void gemm_k(const float* __restrict__ Ag, const float* __restrict__ Bg,
                                              float* __restrict__ Cg, const float* __restrict__ bias,
                                              int M, int N, int K, int lda, int ldb, int ldc,
                                              long sAb, long sAh, long sBb, long sBh,
                                              long sCb, long sCh, int HH, float scale) {
    __shared__ __align__(16) float As[16][64];
    __shared__ __align__(16) float Bs[16][64];
    int z = blockIdx.z;
    int zb = z / HH, zh = z - zb * HH;
    const float* A = Ag + zb * sAb + zh * sAh;
    const float* B = Bg + zb * sBb + zh * sBh;
    float* C = Cg + zb * sCb + zh * sCh;
    int m0 = blockIdx.y * 64, n0 = blockIdx.x * 64;
    float acc[4][4] = {};
    mm_body<TB>(A, B, lda, ldb, K, m0, n0, acc, As, Bs);
    int ty4 = (threadIdx.x >> 4) << 2;
    int tx4 = (threadIdx.x & 15) << 2;
    #pragma unroll
    for (int i = 0; i < 4; i++)
        #pragma unroll
        for (int j = 0; j < 4; j++) {
            int col = n0 + tx4 + j;
            long idx = (long)(m0 + ty4 + i) * ldc + col;
            if (EPI == 0) C[idx] = acc[i][j] * scale;
            else          C[idx] = C[idx] + acc[i][j] + bias[col];
        }
}

// ---------------- LayerNorm ----------------
__global__ __launch_bounds__(256) void ln3_k(const float* __restrict__ X,
                                             const float* __restrict__ wq, const float* __restrict__ bq,
                                             const float* __restrict__ wk, const float* __restrict__ bk,
                                             const float* __restrict__ wv, const float* __restrict__ bv,
                                             float* __restrict__ oq, float* __restrict__ ok,
                                             float* __restrict__ ov) {
    __shared__ float sh[8];
    long row = blockIdx.x;
    const float* xr = X + row * DIMn;
    int t = threadIdx.x;
    float v[4]; float s = 0.f;
    #pragma unroll
    for (int i = 0; i < 4; i++) { v[i] = xr[t + i * 256]; s += v[i]; }
    s = warpSum(s);
    if ((t & 31) == 0) sh[t >> 5] = s;
    __syncthreads();
    if (t < 32) { float a = (t < 8) ? sh[t] : 0.f; a = warpSum(a); if (t == 0) sh[0] = a; }
    __syncthreads();
    float mean = sh[0] * (1.0f / DIMn);
    __syncthreads();
    float ss = 0.f;
    #pragma unroll
    for (int i = 0; i < 4; i++) { float d = v[i] - mean; ss += d * d; }
    ss = warpSum(ss);
    if ((t & 31) == 0) sh[t >> 5] = ss;
    __syncthreads();
    if (t < 32) { float a = (t < 8) ? sh[t] : 0.f; a = warpSum(a); if (t == 0) sh[0] = a; }
    __syncthreads();
    float rstd = rsqrtf(sh[0] * (1.0f / DIMn) + 1e-5f);
    #pragma unroll
    for (int i = 0; i < 4; i++) {
        int c = t + i * 256;
        float xh = (v[i] - mean) * rstd;
        long idx = row * DIMn + c;
        oq[idx] = xh * wq[c] + bq[c];
        ok[idx] = xh * wk[c] + bk[c];
        ov[idx] = xh * wv[c] + bv[c];
    }
}

__global__ __launch_bounds__(256) void ln1_k(const float* __restrict__ X,
                                             const float* __restrict__ w, const float* __restrict__ b,
                                             float* __restrict__ out) {
    __shared__ float sh[8];
    long row = blockIdx.x;
    const float* xr = X + row * DIMn;
    int t = threadIdx.x;
    float v[4]; float s = 0.f;
    #pragma unroll
    for (int i = 0; i < 4; i++) { v[i] = xr[t + i * 256]; s += v[i]; }
    s = warpSum(s);
    if ((t & 31) == 0) sh[t >> 5] = s;
    __syncthreads();
    if (t < 32) { float a = (t < 8) ? sh[t] : 0.f; a = warpSum(a); if (t == 0) sh[0] = a; }
    __syncthreads();
    float mean = sh[0] * (1.0f / DIMn);
    __syncthreads();
    float ss = 0.f;
    #pragma unroll
    for (int i = 0; i < 4; i++) { float d = v[i] - mean; ss += d * d; }
    ss = warpSum(ss);
    if ((t & 31) == 0) sh[t >> 5] = ss;
    __syncthreads();
    if (t < 32) { float a = (t < 8) ? sh[t] : 0.f; a = warpSum(a); if (t == 0) sh[0] = a; }
    __syncthreads();
    float rstd = rsqrtf(sh[0] * (1.0f / DIMn) + 1e-5f);
    #pragma unroll
    for (int i = 0; i < 4; i++) {
        int c = t + i * 256;
        long idx = row * DIMn + c;
        out[idx] = (v[i] - mean) * rstd * w[c] + b[c];
    }
}

// ---------------- softmax over rows of 512 ----------------
__global__ __launch_bounds__(128) void softmax_k(float* __restrict__ S) {
    __shared__ float sh[4];
    long row = blockIdx.x;
    float* p = S + row * 512;
    int t = threadIdx.x;
    float v[4];
    #pragma unroll
    for (int i = 0; i < 4; i++) v[i] = p[t + i * 128];
    float m = fmaxf(fmaxf(v[0], v[1]), fmaxf(v[2], v[3]));
    m = warpMax(m);
    if ((t & 31) == 0) sh[t >> 5] = m;
    __syncthreads();
    if (t < 32) { float a = (t < 4) ? sh[t] : -INFINITY; a = warpMax(a); if (t == 0) sh[0] = a; }
    __syncthreads();
    m = sh[0];
    __syncthreads();
    float s = 0.f;
    #pragma unroll
    for (int i = 0; i < 4; i++) { v[i] = expf(v[i] - m); s += v[i]; }
    s = warpSum(s);
    if ((t & 31) == 0) sh[t >> 5] = s;
    __syncthreads();
    if (t < 32) { float a = (t < 4) ? sh[t] : 0.f; a = warpSum(a); if (t == 0) sh[0] = a; }
    __syncthreads();
    float inv = 1.0f / sh[0];
    #pragma unroll
    for (int i = 0; i < 4; i++) p[t + i * 128] = v[i] * inv;
}

// ---------------- router mean over LR ----------------
__global__ void rimean_k(const float* __restrict__ ri, float* __restrict__ rm) {
    int i = blockIdx.x * 256 + threadIdx.x;   // 8192 total
    int b = i >> 10, d = i & 1023;
    float s = 0.f;
    for (int r = 0; r < LRn; r++) s += ri[((long)b * LRn + r) * DIMn + d];
    rm[i] = s * (1.0f / LRn);
}

// ---------------- router logits ----------------
__global__ __launch_bounds__(256) void logits_k(const float* __restrict__ rm,
                                                const float* __restrict__ Wr, const float* __restrict__ br,
                                                const float* __restrict__ Wn, const float* __restrict__ bn,
                                                float* __restrict__ lg, float* __restrict__ nl) {
    __shared__ float sh[16];
    int b = blockIdx.x >> 3, e = blockIdx.x & 7;
    int t = threadIdx.x;
    float s1 = 0.f, s2 = 0.f;
    for (int d = t; d < DIMn; d += 256) {
        float r = rm[b * DIMn + d];
        s1 += r * Wr[(long)d * En + e];
        s2 += r * Wn[(long)d * En + e];
    }
    s1 = warpSum(s1); s2 = warpSum(s2);
    if ((t & 31) == 0) { sh[t >> 5] = s1; sh[8 + (t >> 5)] = s2; }
    __syncthreads();
    if (t == 0) {
        float a = 0.f, c = 0.f;
        for (int i = 0; i < 8; i++) { a += sh[i]; c += sh[8 + i]; }
        lg[blockIdx.x] = a + br[e];
        nl[blockIdx.x] = c + bn[e];
    }
}

// ---------------- noisy top-k routing + capacity ----------------
// JAX threefry with jax_threefry_partitionable=True (modern default):
// bits[i] = o0 ^ o1 where (o0, o1) = threefry2x32(key, (hi=0, lo=i))
__global__ void route_k(const float* __restrict__ logits, const float* __restrict__ nlog, int l,
                        int* __restrict__ fe, float* __restrict__ fw) {
    __shared__ float sc[64];
    __shared__ int se[16];
    __shared__ float sg[16];
    int t = threadIdx.x;
    if (t < 64) {
        unsigned kk0, kk1;
        tf2x32(0u, 42u, 0u, (unsigned)l, kk0, kk1);       // fold_in(key(42), l)
        unsigned o0, o1;
        tf2x32(kk0, kk1, 0u, (unsigned)t, o0, o1);        // partitionable counter mode
        unsigned bits = o0 ^ o1;
        float f = __uint_as_float(0x3f800000u | (bits >> 9)) - 1.0f;
        const float lo = -0.99999994f;                    // nextafter(-1, 0) fp32
        float u = f * 2.0f + lo;                          // (hi-lo) rounds to exactly 2.0f
        u = fmaxf(lo, u);
        float g = 1.41421356237309515f * erfinvf(u);
        float xnl = nlog[t];
        float sp = fmaxf(xnl, 0.f) + log1pf(expf(-fabsf(xnl)));  // softplus, logaddexp form
        sc[t] = logits[t] + g * sp;
    }
    __syncthreads();
    if (t < 8) {
        const float* row = sc + t * 8;
        int e0 = 0; float v0 = row[0];
        for (int e = 1; e < 8; e++) if (row[e] > v0) { v0 = row[e]; e0 = e; }
        int e1 = -1; float v1 = -INFINITY;
        for (int e = 0; e < 8; e++) if (e != e0 && row[e] > v1) { v1 = row[e]; e1 = e; }
        float d = expf(v1 - v0);
        float inv = 1.0f / (1.0f + d);
        se[t * 2] = e0; se[t * 2 + 1] = e1;
        sg[t * 2] = inv; sg[t * 2 + 1] = d * inv;
    }
    __syncthreads();
    if (t == 0) {
        int cnt[8] = {0, 0, 0, 0, 0, 0, 0, 0};
        for (int n = 0; n < 16; n++) {
            int e = se[n];
            float w = (cnt[e] < CAPn) ? sg[n] : 0.0f;
            cnt[e]++;
            fe[n] = e; fw[n] = w;
        }
    }
}

// ---------------- host launch ----------------
extern "C" void kernel_launch(void* const* d_in, const int* in_sizes, int n_in,
                              void* d_out, int out_size) {
    (void)in_sizes; (void)n_in; (void)out_size;
    const float* router_input = (const float*)d_in[0];
    const float* x0   = (const float*)d_in[1];
    const float* nq_w = (const float*)d_in[2];
    const float* nq_b = (const float*)d_in[3];
    const float* nk_w = (const float*)d_in[4];
    const float* nk_b = (const float*)d_in[5];
    const float* nv_w = (const float*)d_in[6];
    const float* nv_b = (const float*)d_in[7];
    const float* Wq   = (const float*)d_in[8];
    const float* Wk   = (const float*)d_in[9];
    const float* Wv   = (const float*)d_in[10];
    const float* Wo   = (const float*)d_in[11];
    const float* bo   = (const float*)d_in[12];
    const float* nm_w = (const float*)d_in[13];
    const float* nm_b = (const float*)d_in[14];
    const float* Wr   = (const float*)d_in[15];
    const float* br   = (const float*)d_in[16];
    const float* Wn   = (const float*)d_in[17];
    const float* bn   = (const float*)d_in[18];
    const float* W1   = (const float*)d_in[19];
    const float* b1   = (const float*)d_in[20];
    const float* W2   = (const float*)d_in[21];
    const float* b2   = (const float*)d_in[22];

    float* X = (float*)d_out;
    float* arena = nullptr;
    cudaGetSymbolAddress((void**)&arena, g_arena);
    float* lnq = arena + O_LNQ;
    float* lnk = arena + O_LNK;
    float* lnv = arena + O_LNV;
    float* qb  = arena + O_Q;
    float* kb  = arena + O_K;
    float* vb  = arena + O_V;
    float* ob  = arena + O_O;
    float* xn  = arena + O_XN;
    float* sc  = arena + O_SC;
    float* hb  = arena + O_H;
    float* rm  = arena + O_RM;
    float* lg  = arena + O_LG;
    float* nl  = arena + O_NL;
    float* fw  = arena + O_FW;
    int*   fe  = (int*)(arena + O_FE);

    cudaMemcpyAsync(X, x0, sizeof(float) * SZX, cudaMemcpyDeviceToDevice);
    rimean_k<<<32, 256>>>(router_input, rm);

    const long sQb = (long)Ssz * INNERn;   // per-batch stride in q/k/v/o
    const long sQh = DHn;                  // per-head stride
    const long sScb = (long)Hn * Ssz * Ssz;
    const long sSch = (long)Ssz * Ssz;

    for (int l = 0; l < Dlay; l++) {
        const float* Wq_l = Wq + (long)l * DIMn * INNERn;
        const float* Wk_l = Wk + (long)l * DIMn * INNERn;
        const float* Wv_l = Wv + (long)l * DIMn * INNERn;
        const float* Wo_l = Wo + (long)l * INNERn * DIMn;

        ln3_k<<<Bn * Ssz, 256>>>(X, nq_w + l * DIMn, nq_b + l * DIMn,
                                 nk_w + l * DIMn, nk_b + l * DIMn,
                                 nv_w + l * DIMn, nv_b + l * DIMn, lnq, lnk, lnv);

        // QKV projections (tf32 tensor cores)
        wgemm_k<0><<<dim3(INNERn / 128, Bn * Ssz / 128), 256>>>(lnq, Wq_l, qb, nullptr,
                                                                DIMn, DIMn, INNERn, INNERn);
        wgemm_k<0><<<dim3(INNERn / 128, Bn * Ssz / 128), 256>>>(lnk, Wk_l, kb, nullptr,
                                                                DIMn, DIMn, INNERn, INNERn);
        wgemm_k<0><<<dim3(INNERn / 128, Bn * Ssz / 128), 256>>>(lnv, Wv_l, vb, nullptr,
                                                                DIMn, DIMn, INNERn, INNERn);

        // scores = Q K^T * scale  (batched over B*H, FFMA path)
        gemm_k<0, true><<<dim3(Ssz / 64, Ssz / 64, Bn * Hn), 256>>>(
            qb, kb, sc, nullptr, Ssz, Ssz, DHn, INNERn, INNERn, Ssz,
            sQb, sQh, sQb, sQh, sScb, sSch, Hn, 0.125f);

        softmax_k<<<Bn * Hn * Ssz, 128>>>(sc);

        // O = P V (FFMA path)
        gemm_k<0, false><<<dim3(1, Ssz / 64, Bn * Hn), 256>>>(
            sc, vb, ob, nullptr, Ssz, DHn, Ssz, Ssz, INNERn, INNERn,
            sScb, sSch, sQb, sQh, sQb, sQh, Hn, 1.0f);

        // X += O @ Wo + bo (tf32 tensor cores, fused residual)
        wgemm_k<1><<<dim3(DIMn / 128, Bn * Ssz / 128), 256>>>(ob, Wo_l, X, bo + l * DIMn,
                                                              INNERn, INNERn, DIMn, DIMn);

        // routing
        logits_k<<<Bn * En, 256>>>(rm, Wr + (long)l * DIMn * En, br + l * En,
                                   Wn + (long)l * DIMn * En, bn + l * En, lg, nl);
        route_k<<<1, 64>>>(lg, nl, l, fe, fw);

        // MoE (tf32 tensor cores)
        ln1_k<<<Bn * Ssz, 256>>>(X, nm_w + l * DIMn, nm_b + l * DIMn, xn);
        moe1_w<<<dim3(MLPn / 128, Ssz / 128, Bn * Kn), 256>>>(
            xn, W1 + (long)l * En * DIMn * MLPn, b1 + (long)l * En * MLPn, hb, fe, fw);
        moe2_w<<<dim3(DIMn / 128, Ssz / 128, Bn * Kn), 256>>>(
            hb, W2 + (long)l * En * MLPn * DIMn, b2 + (long)l * En * DIMn, X, fe, fw);
    }
}

// round 4
// speedup vs baseline: 1.4393x; 1.0041x over previous
#include <cuda_runtime.h>
#include <math.h>
#include <mma.h>

using namespace nvcuda;

// ---------------- problem constants ----------------
#define Bn     8
#define Ssz    512
#define DIMn   1024
#define Hn     16
#define DHn    64
#define INNERn 1024
#define MLPn   4096
#define En     8
#define Kn     2
#define LRn    77
#define CAPn   2
#define Dlay   2

static const long SZX = (long)Bn * Ssz * DIMn;           // 4,194,304
static const long SZSC = (long)Bn * Hn * Ssz * Ssz;      // 33,554,432
static const long SZH  = (long)Bn * Kn * Ssz * MLPn;     // 33,554,432

// arena offsets (floats)
static const long O_LNQ = 0;
static const long O_LNK = O_LNQ + SZX;
static const long O_LNV = O_LNK + SZX;
static const long O_Q   = O_LNV + SZX;
static const long O_K   = O_Q   + SZX;
static const long O_V   = O_K   + SZX;
static const long O_O   = O_V   + SZX;
static const long O_XN  = O_O   + SZX;
static const long O_SC  = O_XN  + SZX;
static const long O_H   = O_SC  + SZSC;
static const long O_RM  = O_H   + SZH;            // 8*1024
static const long O_LG  = O_RM  + 8192;           // 64
static const long O_NL  = O_LG  + 64;             // 64
static const long O_FW  = O_NL  + 64;             // 16
static const long O_FE  = O_FW  + 16;             // 16 ints
static const long ARENA_FLOATS = O_FE + 64;

__device__ __align__(16) float g_arena[ARENA_FLOATS];

// ---------------- reductions ----------------
__device__ __forceinline__ float warpSum(float v) {
    #pragma unroll
    for (int o = 16; o; o >>= 1) v += __shfl_xor_sync(0xffffffffu, v, o);
    return v;
}
__device__ __forceinline__ float warpMax(float v) {
    #pragma unroll
    for (int o = 16; o; o >>= 1) v = fmaxf(v, __shfl_xor_sync(0xffffffffu, v, o));
    return v;
}

// ---------------- threefry2x32 (JAX-exact) ----------------
__device__ __forceinline__ void tf2x32(unsigned k0, unsigned k1, unsigned x0, unsigned x1,
                                       unsigned& o0, unsigned& o1) {
    unsigned ks0 = k0, ks1 = k1, ks2 = k0 ^ k1 ^ 0x1BD11BDAu;
    unsigned ks[3] = {ks0, ks1, ks2};
    const int R0[4] = {13, 15, 26, 6};
    const int R1[4] = {17, 29, 16, 24};
    x0 += ks[0]; x1 += ks[1];
    #pragma unroll
    for (int i = 0; i < 5; i++) {
        #pragma unroll
        for (int r = 0; r < 4; r++) {
            int rot = (i & 1) ? R1[r] : R0[r];
            x0 += x1;
            x1 = (x1 << rot) | (x1 >> (32 - rot));
            x1 ^= x0;
        }
        x0 += ks[(i + 1) % 3];
        x1 += ks[(i + 2) % 3] + (unsigned)(i + 1);
    }
    o0 = x0; o1 = x1;
}

// =================================================================
// WMMA tf32 GEMM: 128x128 CTA, BK=32, 8 warps (4Mx2N), warp 32x64,
// cp.async double-buffered, tf32 cvt on fragment registers.
// =================================================================
using FragA = wmma::fragment<wmma::matrix_a, 16, 16, 8, wmma::precision::tf32, wmma::row_major>;
using FragB = wmma::fragment<wmma::matrix_b, 16, 16, 8, wmma::precision::tf32, wmma::row_major>;
using FragC = wmma::fragment<wmma::accumulator, 16, 16, 8, float>;

__device__ __forceinline__ float tf32r(float x) { return wmma::__float_to_tf32(x); }

__device__ __forceinline__ void cpa16(float* dst_smem, const float* src) {
    unsigned d = (unsigned)__cvta_generic_to_shared(dst_smem);
    asm volatile("cp.async.cg.shared.global [%0], [%1], 16;\n" :: "r"(d), "l"(src));
}
__device__ __forceinline__ void cp_commit() { asm volatile("cp.async.commit_group;\n"); }
template <int N>
__device__ __forceinline__ void cp_wait() { asm volatile("cp.async.wait_group %0;\n" :: "n"(N)); }

// smem layout (floats): sA[2][128*36], sB[2][32*132]  => 17664 floats = 70656 B
#define SA_STRIDE 36
#define SB_STRIDE 132
#define SA_STAGE  (128 * SA_STRIDE)
#define SB_STAGE  (32 * SB_STRIDE)
static const int SMEMW_BYTES = (2 * SA_STAGE + 2 * SB_STAGE) * 4;

__device__ __forceinline__ void wmm_cp(const float* __restrict__ A, const float* __restrict__ B,
                                       int lda, int ldb, int K, int m0, int n0,
                                       float* sm, FragC (&acc)[2][4]) {
    float* sA[2] = { sm, sm + SA_STAGE };
    float* sB[2] = { sm + 2 * SA_STAGE, sm + 2 * SA_STAGE + SB_STAGE };
    int tid = threadIdx.x;
    int warp = tid >> 5, wm = warp & 3, wn = warp >> 2;
    int arow = tid >> 1, acol = (tid & 1) * 16;   // 4 float4 chunks per thread
    int brow = tid >> 3, bcol = (tid & 7) * 16;
    const float* Ab = A + (long)(m0 + arow) * lda + acol;
    const float* Bb = B + (long)brow * ldb + n0 + bcol;
    float* dA[2] = { sA[0] + arow * SA_STRIDE + acol, sA[1] + arow * SA_STRIDE + acol };
    float* dB[2] = { sB[0] + brow * SB_STRIDE + bcol, sB[1] + brow * SB_STRIDE + bcol };

    int nIt = K >> 5;
    // prefetch stage 0
    {
        #pragma unroll
        for (int i = 0; i < 4; i++) cpa16(dA[0] + i * 4, Ab + i * 4);
        #pragma unroll
        for (int i = 0; i < 4; i++) cpa16(dB[0] + i * 4, Bb + i * 4);
        cp_commit();
    }
    #pragma unroll 1
    for (int it = 0; it < nIt; it++) {
        int s = it & 1;
        if (it + 1 < nIt) {
            int s2 = s ^ 1;
            const float* a = Ab + (it + 1) * 32;
            const float* b = Bb + (long)(it + 1) * 32 * ldb;
            #pragma unroll
            for (int i = 0; i < 4; i++) cpa16(dA[s2] + i * 4, a + i * 4);
            #pragma unroll
            for (int i = 0; i < 4; i++) cpa16(dB[s2] + i * 4, b + i * 4);
            cp_commit();
            cp_wait<1>();
        } else {
            cp_wait<0>();
        }
        __syncthreads();
        #pragma unroll
        for (int kk = 0; kk < 4; kk++) {
            FragA af[2];
            FragB bf[4];
            #pragma unroll
            for (int i = 0; i < 2; i++) {
                wmma::load_matrix_sync(af[i], sA[s] + (wm * 32 + i * 16) * SA_STRIDE + kk * 8, SA_STRIDE);
                #pragma unroll
                for (int e = 0; e < af[i].num_elements; e++) af[i].x[e] = tf32r(af[i].x[e]);
            }
            #pragma unroll
            for (int j = 0; j < 4; j++) {
                wmma::load_matrix_sync(bf[j], sB[s] + (kk * 8) * SB_STRIDE + wn * 64 + j * 16, SB_STRIDE);
                #pragma unroll
                for (int e = 0; e < bf[j].num_elements; e++) bf[j].x[e] = tf32r(bf[j].x[e]);
            }
            #pragma unroll
            for (int i = 0; i < 2; i++)
                #pragma unroll
                for (int j = 0; j < 4; j++)
                    wmma::mma_sync(acc[i][j], af[i], bf[j], acc[i][j]);
        }
        __syncthreads();
    }
}

// EPI: 1 = C += acc + bias ; 2 = C = gelu(acc + bias) ; 3 = atomicAdd(C, (acc+bias)*w)
template <int EPI>
__device__ __forceinline__ void wepilogue(FragC (&acc)[2][4], float* stage_w,
                                          float* __restrict__ C, const float* __restrict__ bias,
                                          int ldc, int m0, int n0, float w) {
    int tid = threadIdx.x, warp = tid >> 5, lane = tid & 31;
    int wm = warp & 3, wn = warp >> 2;
    int r = lane >> 1, cb = (lane & 1) * 8;
    #pragma unroll
    for (int i = 0; i < 2; i++)
        #pragma unroll
        for (int j = 0; j < 4; j++) {
            wmma::store_matrix_sync(stage_w, acc[i][j], 20, wmma::mem_row_major);
            __syncwarp();
            int row = m0 + wm * 32 + i * 16 + r;
            int col0 = n0 + wn * 64 + j * 16 + cb;
            #pragma unroll
            for (int c = 0; c < 8; c++) {
                float v = stage_w[r * 20 + cb + c];
                int col = col0 + c;
                long idx = (long)row * ldc + col;
                if (EPI == 1) C[idx] = C[idx] + v + bias[col];
                else if (EPI == 2) {
                    float u = v + bias[col];
                    C[idx] = 0.5f * u * (1.0f + erff(u * 0.70710678118654752f));
                } else {
                    atomicAdd(&C[idx], (v + bias[col]) * w);
                }
            }
            __syncwarp();
        }
}

__device__ __forceinline__ void acc_zero(FragC (&acc)[2][4]) {
    #pragma unroll
    for (int i = 0; i < 2; i++)
        #pragma unroll
        for (int j = 0; j < 4; j++) wmma::fill_fragment(acc[i][j], 0.0f);
}

// fused QKV: z selects (lnq,Wq,q) / (lnk,Wk,k) / (lnv,Wv,v)
__global__ __launch_bounds__(256, 2) void qkv_w(const float* __restrict__ lnq, const float* __restrict__ lnk,
                                                const float* __restrict__ lnv,
                                                const float* __restrict__ Wq, const float* __restrict__ Wk,
                                                const float* __restrict__ Wv,
                                                float* __restrict__ q, float* __restrict__ k,
                                                float* __restrict__ v) {
    extern __shared__ float sm[];
    int z = blockIdx.z;
    const float* A = (z == 0) ? lnq : (z == 1) ? lnk : lnv;
    const float* B = (z == 0) ? Wq : (z == 1) ? Wk : Wv;
    float* C = (z == 0) ? q : (z == 1) ? k : v;
    int m0 = blockIdx.y * 128, n0 = blockIdx.x * 128;
    FragC acc[2][4];
    acc_zero(acc);
    wmm_cp(A, B, DIMn, INNERn, DIMn, m0, n0, sm, acc);
    int warp = threadIdx.x >> 5, wm = warp & 3, wn = warp >> 2;
    #pragma unroll
    for (int i = 0; i < 2; i++)
        #pragma unroll
        for (int j = 0; j < 4; j++)
            wmma::store_matrix_sync(&C[(long)(m0 + wm * 32 + i * 16) * INNERn + n0 + wn * 64 + j * 16],
                                    acc[i][j], INNERn, wmma::mem_row_major);
}

// X += O @ Wo + bo
__global__ __launch_bounds__(256, 2) void wo_w(const float* __restrict__ A, const float* __restrict__ B,
                                               float* __restrict__ C, const float* __restrict__ bias) {
    extern __shared__ float sm[];
    int m0 = blockIdx.y * 128, n0 = blockIdx.x * 128;
    FragC acc[2][4];
    acc_zero(acc);
    wmm_cp(A, B, INNERn, DIMn, INNERn, m0, n0, sm, acc);
    float* stage = sm + (threadIdx.x >> 5) * 320;   // alias pipeline buffers (safe after final barrier)
    wepilogue<1>(acc, stage, C, bias, DIMn, m0, n0, 0.0f);
}

// MoE first GEMM: H = gelu(xn[slot] @ W1[e] + b1[e])
__global__ __launch_bounds__(256, 2) void moe1_w(const float* __restrict__ xn, const float* __restrict__ W1l,
                                                 const float* __restrict__ b1l, float* __restrict__ H,
                                                 const int* __restrict__ fe, const float* __restrict__ fw) {
    extern __shared__ float sm[];
    int n = blockIdx.z;
    if (fw[n] == 0.0f) return;
    int e = fe[n];
    const float* A = xn + (long)(n >> 1) * Ssz * DIMn;
    const float* B = W1l + (long)e * DIMn * MLPn;
    float* C = H + (long)n * Ssz * MLPn;
    const float* bias = b1l + (long)e * MLPn;
    int m0 = blockIdx.y * 128, n0 = blockIdx.x * 128;
    FragC acc[2][4];
    acc_zero(acc);
    wmm_cp(A, B, DIMn, MLPn, DIMn, m0, n0, sm, acc);
    float* stage = sm + (threadIdx.x >> 5) * 320;
    wepilogue<2>(acc, stage, C, bias, MLPn, m0, n0, 0.0f);
}

// MoE second GEMM: X[slot>>1] += (H[slot] @ W2[e] + b2[e]) * w
__global__ __launch_bounds__(256, 2) void moe2_w(const float* __restrict__ H, const float* __restrict__ W2l,
                                                 const float* __restrict__ b2l, float* __restrict__ X,
                                                 const int* __restrict__ fe, const float* __restrict__ fw) {
    extern __shared__ float sm[];
    int n = blockIdx.z;
    float w = fw[n];
    if (w == 0.0f) return;
    int e = fe[n];
    const float* A = H + (long)n * Ssz * MLPn;
    const float* B = W2l + (long)e * MLPn * DIMn;
    float* C = X + (long)(n >> 1) * Ssz * DIMn;
    const float* bias = b2l + (long)e * DIMn;
    int m0 = blockIdx.y * 128, n0 = blockIdx.x * 128;
    FragC acc[2][4];
    acc_zero(acc);
    wmm_cp(A, B, MLPn, DIMn, MLPn, m0, n0, sm, acc);
    float* stage = sm + (threadIdx.x >> 5) * 320;
    wepilogue<3>(acc, stage, C, bias, DIMn, m0, n0, w);
}

// ---------------- FFMA GEMM (attention only): 64x64x16 tile ----------------
template <bool TB>
__device__ __forceinline__ void mm_body(const float* __restrict__ A, const float* __restrict__ B,
                                        int lda, int ldb, int K, int m0, int n0,
                                        float (&acc)[4][4], float (*As)[64], float (*Bs)[64]) {
    int tid = threadIdx.x;
    int ar = tid >> 2;
    int ac = (tid & 3) << 2;
    int ty4 = (tid >> 4) << 2;
    int tx4 = (tid & 15) << 2;
    for (int k0 = 0; k0 < K; k0 += 16) {
        float4 a4 = *(const float4*)(A + (long)(m0 + ar) * lda + k0 + ac);
        As[ac + 0][ar] = a4.x; As[ac + 1][ar] = a4.y;
        As[ac + 2][ar] = a4.z; As[ac + 3][ar] = a4.w;
        if (TB) {
            float4 b4 = *(const float4*)(B + (long)(n0 + ar) * ldb + k0 + ac);
            Bs[ac + 0][ar] = b4.x; Bs[ac + 1][ar] = b4.y;
            Bs[ac + 2][ar] = b4.z; Bs[ac + 3][ar] = b4.w;
        } else {
            int rb = tid >> 4;
            int cb = (tid & 15) << 2;
            *(float4*)&Bs[rb][cb] = *(const float4*)(B + (long)(k0 + rb) * ldb + n0 + cb);
        }
        __syncthreads();
        #pragma unroll
        for (int kk = 0; kk < 16; kk++) {
            float4 av = *(const float4*)&As[kk][ty4];
            float4 bv = *(const float4*)&Bs[kk][tx4];
            float a0[4] = {av.x, av.y, av.z, av.w};
            float b0[4] = {bv.x, bv.y, bv.z, bv.w};
            #pragma unroll
            for (int i = 0; i < 4; i++)
                #pragma unroll
                for (int j = 0; j < 4; j++)
                    acc[i][j] += a0[i] * b0[j];
        }
        __syncthreads();
    }
}

template <int EPI, bool TB>
__global__ __launch_bounds__(256) void gemm_k(const float* __restrict__ Ag, const float* __restrict__ Bg,
                                              float* __restrict__ Cg, const float* __restrict__ bias,
                                              int M, int N, int K, int lda, int ldb, int ldc,
                                              long sAb, long sAh, long sBb, long sBh,
                                              long sCb, long sCh, int HH, float scale) {
    __shared__ __align__(16) float As[16][64];
    __shared__ __align__(16) float Bs[16][64];
    int z = blockIdx.z;
    int zb = z / HH, zh = z - zb * HH;
    const float* A = Ag + zb * sAb + zh * sAh;
    const float* B = Bg + zb * sBb + zh * sBh;
    float* C = Cg + zb * sCb + zh * sCh;
    int m0 = blockIdx.y * 64, n0 = blockIdx.x * 64;
    float acc[4][4] = {};
    mm_body<TB>(A, B, lda, ldb, K, m0, n0, acc, As, Bs);
    int ty4 = (threadIdx.x >> 4) << 2;
    int tx4 = (threadIdx.x & 15) << 2;
    #pragma unroll
    for (int i = 0; i < 4; i++)
        #pragma unroll
        for (int j = 0; j < 4; j++) {
            int col = n0 + tx4 + j;
            long idx = (long)(m0 + ty4 + i) * ldc + col;
            if (EPI == 0) C[idx] = acc[i][j] * scale;
            else          C[idx] = C[idx] + acc[i][j] + bias[col];
        }
}

// ---------------- LayerNorm ----------------
__global__ __launch_bounds__(256) void ln3_k(const float* __restrict__ X,
                                             const float* __restrict__ wq, const float* __restrict__ bq,
                                             const float* __restrict__ wk, const float* __restrict__ bk,
                                             const float* __restrict__ wv, const float* __restrict__ bv,
                                             float* __restrict__ oq, float* __restrict__ ok,
                                             float* __restrict__ ov) {
    __shared__ float sh[8];
    long row = blockIdx.x;
    const float* xr = X + row * DIMn;
    int t = threadIdx.x;
    float v[4]; float s = 0.f;
    #pragma unroll
    for (int i = 0; i < 4; i++) { v[i] = xr[t + i * 256]; s += v[i]; }
    s = warpSum(s);
    if ((t & 31) == 0) sh[t >> 5] = s;
    __syncthreads();
    if (t < 32) { float a = (t < 8) ? sh[t] : 0.f; a = warpSum(a); if (t == 0) sh[0] = a; }
    __syncthreads();
    float mean = sh[0] * (1.0f / DIMn);
    __syncthreads();
    float ss = 0.f;
    #pragma unroll
    for (int i = 0; i < 4; i++) { float d = v[i] - mean; ss += d * d; }
    ss = warpSum(ss);
    if ((t & 31) == 0) sh[t >> 5] = ss;
    __syncthreads();
    if (t < 32) { float a = (t < 8) ? sh[t] : 0.f; a = warpSum(a); if (t == 0) sh[0] = a; }
    __syncthreads();
    float rstd = rsqrtf(sh[0] * (1.0f / DIMn) + 1e-5f);
    #pragma unroll
    for (int i = 0; i < 4; i++) {
        int c = t + i * 256;
        float xh = (v[i] - mean) * rstd;
        long idx = row * DIMn + c;
        oq[idx] = xh * wq[c] + bq[c];
        ok[idx] = xh * wk[c] + bk[c];
        ov[idx] = xh * wv[c] + bv[c];
    }
}

__global__ __launch_bounds__(256) void ln1_k(const float* __restrict__ X,
                                             const float* __restrict__ w, const float* __restrict__ b,
                                             float* __restrict__ out) {
    __shared__ float sh[8];
    long row = blockIdx.x;
    const float* xr = X + row * DIMn;
    int t = threadIdx.x;
    float v[4]; float s = 0.f;
    #pragma unroll
    for (int i = 0; i < 4; i++) { v[i] = xr[t + i * 256]; s += v[i]; }
    s = warpSum(s);
    if ((t & 31) == 0) sh[t >> 5] = s;
    __syncthreads();
    if (t < 32) { float a = (t < 8) ? sh[t] : 0.f; a = warpSum(a); if (t == 0) sh[0] = a; }
    __syncthreads();
    float mean = sh[0] * (1.0f / DIMn);
    __syncthreads();
    float ss = 0.f;
    #pragma unroll
    for (int i = 0; i < 4; i++) { float d = v[i] - mean; ss += d * d; }
    ss = warpSum(ss);
    if ((t & 31) == 0) sh[t >> 5] = ss;
    __syncthreads();
    if (t < 32) { float a = (t < 8) ? sh[t] : 0.f; a = warpSum(a); if (t == 0) sh[0] = a; }
    __syncthreads();
    float rstd = rsqrtf(sh[0] * (1.0f / DIMn) + 1e-5f);
    #pragma unroll
    for (int i = 0; i < 4; i++) {
        int c = t + i * 256;
        long idx = row * DIMn + c;
        out[idx] = (v[i] - mean) * rstd * w[c] + b[c];
    }
}

// ---------------- softmax over rows of 512 ----------------
__global__ __launch_bounds__(128) void softmax_k(float* __restrict__ S) {
    __shared__ float sh[4];
    long row = blockIdx.x;
    float* p = S + row * 512;
    int t = threadIdx.x;
    float v[4];
    #pragma unroll
    for (int i = 0; i < 4; i++) v[i] = p[t + i * 128];
    float m = fmaxf(fmaxf(v[0], v[1]), fmaxf(v[2], v[3]));
    m = warpMax(m);
    if ((t & 31) == 0) sh[t >> 5] = m;
    __syncthreads();
    if (t < 32) { float a = (t < 4) ? sh[t] : -INFINITY; a = warpMax(a); if (t == 0) sh[0] = a; }
    __syncthreads();
    m = sh[0];
    __syncthreads();
    float s = 0.f;
    #pragma unroll
    for (int i = 0; i < 4; i++) { v[i] = expf(v[i] - m); s += v[i]; }
    s = warpSum(s);
    if ((t & 31) == 0) sh[t >> 5] = s;
    __syncthreads();
    if (t < 32) { float a = (t < 4) ? sh[t] : 0.f; a = warpSum(a); if (t == 0) sh[0] = a; }
    __syncthreads();
    float inv = 1.0f / sh[0];
    #pragma unroll
    for (int i = 0; i < 4; i++) p[t + i * 128] = v[i] * inv;
}

// ---------------- router mean over LR ----------------
__global__ void rimean_k(const float* __restrict__ ri, float* __restrict__ rm) {
    int i = blockIdx.x * 256 + threadIdx.x;   // 8192 total
    int b = i >> 10, d = i & 1023;
    float s = 0.f;
    for (int r = 0; r < LRn; r++) s += ri[((long)b * LRn + r) * DIMn + d];
    rm[i] = s * (1.0f / LRn);
}

// ---------------- router logits ----------------
__global__ __launch_bounds__(256) void logits_k(const float* __restrict__ rm,
                                                const float* __restrict__ Wr, const float* __restrict__ br,
                                                const float* __restrict__ Wn, const float* __restrict__ bn,
                                                float* __restrict__ lg, float* __restrict__ nl) {
    __shared__ float sh[16];
    int b = blockIdx.x >> 3, e = blockIdx.x & 7;
    int t = threadIdx.x;
    float s1 = 0.f, s2 = 0.f;
    for (int d = t; d < DIMn; d += 256) {
        float r = rm[b * DIMn + d];
        s1 += r * Wr[(long)d * En + e];
        s2 += r * Wn[(long)d * En + e];
    }
    s1 = warpSum(s1); s2 = warpSum(s2);
    if ((t & 31) == 0) { sh[t >> 5] = s1; sh[8 + (t >> 5)] = s2; }
    __syncthreads();
    if (t == 0) {
        float a = 0.f, c = 0.f;
        for (int i = 0; i < 8; i++) { a += sh[i]; c += sh[8 + i]; }
        lg[blockIdx.x] = a + br[e];
        nl[blockIdx.x] = c + bn[e];
    }
}

// ---------------- noisy top-k routing + capacity ----------------
// JAX threefry with jax_threefry_partitionable=True (modern default):
// bits[i] = o0 ^ o1 where (o0, o1) = threefry2x32(key, (hi=0, lo=i))
__global__ void route_k(const float* __restrict__ logits, const float* __restrict__ nlog, int l,
                        int* __restrict__ fe, float* __restrict__ fw) {
    __shared__ float sc[64];
    __shared__ int se[16];
    __shared__ float sg[16];
    int t = threadIdx.x;
    if (t < 64) {
        unsigned kk0, kk1;
        tf2x32(0u, 42u, 0u, (unsigned)l, kk0, kk1);       // fold_in(key(42), l)
        unsigned o0, o1;
        tf2x32(kk0, kk1, 0u, (unsigned)t, o0, o1);        // partitionable counter mode
        unsigned bits = o0 ^ o1;
        float f = __uint_as_float(0x3f800000u | (bits >> 9)) - 1.0f;
        const float lo = -0.99999994f;                    // nextafter(-1, 0) fp32
        float u = f * 2.0f + lo;                          // (hi-lo) rounds to exactly 2.0f
        u = fmaxf(lo, u);
        float g = 1.41421356237309515f * erfinvf(u);
        float xnl = nlog[t];
        float sp = fmaxf(xnl, 0.f) + log1pf(expf(-fabsf(xnl)));  // softplus, logaddexp form
        sc[t] = logits[t] + g * sp;
    }
    __syncthreads();
    if (t < 8) {
        const float* row = sc + t * 8;
        int e0 = 0; float v0 = row[0];
        for (int e = 1; e < 8; e++) if (row[e] > v0) { v0 = row[e]; e0 = e; }
        int e1 = -1; float v1 = -INFINITY;
        for (int e = 0; e < 8; e++) if (e != e0 && row[e] > v1) { v1 = row[e]; e1 = e; }
        float d = expf(v1 - v0);
        float inv = 1.0f / (1.0f + d);
        se[t * 2] = e0; se[t * 2 + 1] = e1;
        sg[t * 2] = inv; sg[t * 2 + 1] = d * inv;
    }
    __syncthreads();
    if (t == 0) {
        int cnt[8] = {0, 0, 0, 0, 0, 0, 0, 0};
        for (int n = 0; n < 16; n++) {
            int e = se[n];
            float w = (cnt[e] < CAPn) ? sg[n] : 0.0f;
            cnt[e]++;
            fe[n] = e; fw[n] = w;
        }
    }
}

// ---------------- host launch ----------------
extern "C" void kernel_launch(void* const* d_in, const int* in_sizes, int n_in,
                              void* d_out, int out_size) {
    (void)in_sizes; (void)n_in; (void)out_size;
    const float* router_input = (const float*)d_in[0];
    const float* x0   = (const float*)d_in[1];
    const float* nq_w = (const float*)d_in[2];
    const float* nq_b = (const float*)d_in[3];
    const float* nk_w = (const float*)d_in[4];
    const float* nk_b = (const float*)d_in[5];
    const float* nv_w = (const float*)d_in[6];
    const float* nv_b = (const float*)d_in[7];
    const float* Wq   = (const float*)d_in[8];
    const float* Wk   = (const float*)d_in[9];
    const float* Wv   = (const float*)d_in[10];
    const float* Wo   = (const float*)d_in[11];
    const float* bo   = (const float*)d_in[12];
    const float* nm_w = (const float*)d_in[13];
    const float* nm_b = (const float*)d_in[14];
    const float* Wr   = (const float*)d_in[15];
    const float* br   = (const float*)d_in[16];
    const float* Wn   = (const float*)d_in[17];
    const float* bn   = (const float*)d_in[18];
    const float* W1   = (const float*)d_in[19];
    const float* b1   = (const float*)d_in[20];
    const float* W2   = (const float*)d_in[21];
    const float* b2   = (const float*)d_in[22];

    float* X = (float*)d_out;
    float* arena = nullptr;
    cudaGetSymbolAddress((void**)&arena, g_arena);
    float* lnq = arena + O_LNQ;
    float* lnk = arena + O_LNK;
    float* lnv = arena + O_LNV;
    float* qb  = arena + O_Q;
    float* kb  = arena + O_K;
    float* vb  = arena + O_V;
    float* ob  = arena + O_O;
    float* xn  = arena + O_XN;
    float* sc  = arena + O_SC;
    float* hb  = arena + O_H;
    float* rm  = arena + O_RM;
    float* lg  = arena + O_LG;
    float* nl  = arena + O_NL;
    float* fw  = arena + O_FW;
    int*   fe  = (int*)(arena + O_FE);

    cudaFuncSetAttribute(qkv_w, cudaFuncAttributeMaxDynamicSharedMemorySize, SMEMW_BYTES);
    cudaFuncSetAttribute(wo_w, cudaFuncAttributeMaxDynamicSharedMemorySize, SMEMW_BYTES);
    cudaFuncSetAttribute(moe1_w, cudaFuncAttributeMaxDynamicSharedMemorySize, SMEMW_BYTES);
    cudaFuncSetAttribute(moe2_w, cudaFuncAttributeMaxDynamicSharedMemorySize, SMEMW_BYTES);

    cudaMemcpyAsync(X, x0, sizeof(float) * SZX, cudaMemcpyDeviceToDevice);
    rimean_k<<<32, 256>>>(router_input, rm);

    const long sQb = (long)Ssz * INNERn;   // per-batch stride in q/k/v/o
    const long sQh = DHn;                  // per-head stride
    const long sScb = (long)Hn * Ssz * Ssz;
    const long sSch = (long)Ssz * Ssz;

    for (int l = 0; l < Dlay; l++) {
        const float* Wq_l = Wq + (long)l * DIMn * INNERn;
        const float* Wk_l = Wk + (long)l * DIMn * INNERn;
        const float* Wv_l = Wv + (long)l * DIMn * INNERn;
        const float* Wo_l = Wo + (long)l * INNERn * DIMn;

        ln3_k<<<Bn * Ssz, 256>>>(X, nq_w + l * DIMn, nq_b + l * DIMn,
                                 nk_w + l * DIMn, nk_b + l * DIMn,
                                 nv_w + l * DIMn, nv_b + l * DIMn, lnq, lnk, lnv);

        // QKV projections fused into one launch (tf32 tensor cores)
        qkv_w<<<dim3(INNERn / 128, Bn * Ssz / 128, 3), 256, SMEMW_BYTES>>>(
            lnq, lnk, lnv, Wq_l, Wk_l, Wv_l, qb, kb, vb);

        // scores = Q K^T * scale  (batched over B*H, FFMA path)
        gemm_k<0, true><<<dim3(Ssz / 64, Ssz / 64, Bn * Hn), 256>>>(
            qb, kb, sc, nullptr, Ssz, Ssz, DHn, INNERn, INNERn, Ssz,
            sQb, sQh, sQb, sQh, sScb, sSch, Hn, 0.125f);

        softmax_k<<<Bn * Hn * Ssz, 128>>>(sc);

        // O = P V (FFMA path)
        gemm_k<0, false><<<dim3(1, Ssz / 64, Bn * Hn), 256>>>(
            sc, vb, ob, nullptr, Ssz, DHn, Ssz, Ssz, INNERn, INNERn,
            sScb, sSch, sQb, sQh, sQb, sQh, Hn, 1.0f);

        // X += O @ Wo + bo (tf32, fused residual)
        wo_w<<<dim3(DIMn / 128, Bn * Ssz / 128), 256, SMEMW_BYTES>>>(ob, Wo_l, X, bo + l * DIMn);

        // routing
        logits_k<<<Bn * En, 256>>>(rm, Wr + (long)l * DIMn * En, br + l * En,
                                   Wn + (long)l * DIMn * En, bn + l * En, lg, nl);
        route_k<<<1, 64>>>(lg, nl, l, fe, fw);

        // MoE (tf32 tensor cores)
        ln1_k<<<Bn * Ssz, 256>>>(X, nm_w + l * DIMn, nm_b + l * DIMn, xn);
        moe1_w<<<dim3(MLPn / 128, Ssz / 128, Bn * Kn), 256, SMEMW_BYTES>>>(
            xn, W1 + (long)l * En * DIMn * MLPn, b1 + (long)l * En * MLPn, hb, fe, fw);
        moe2_w<<<dim3(DIMn / 128, Ssz / 128, Bn * Kn), 256, SMEMW_BYTES>>>(
            hb, W2 + (long)l * En * MLPn * DIMn, b2 + (long)l * En * DIMn, X, fe, fw);
    }
}

// round 5
// speedup vs baseline: 3.0428x; 2.1140x over previous
#include <cuda_runtime.h>
#include <cuda_fp16.h>
#include <math.h>
#include <mma.h>

using namespace nvcuda;

// ---------------- problem constants ----------------
#define Bn     8
#define Ssz    512
#define DIMn   1024
#define Hn     16
#define DHn    64
#define INNERn 1024
#define MLPn   4096
#define En     8
#define Kn     2
#define LRn    77
#define CAPn   2
#define Dlay   2

static const long SZX = (long)Bn * Ssz * DIMn;           // 4,194,304
static const long SZSC = (long)Bn * Hn * Ssz * Ssz;      // 33,554,432
static const long SZH  = (long)Bn * Kn * Ssz * MLPn;     // 33,554,432

// ---- fp32 arena ----
static const long O_Q   = 0;
static const long O_K   = O_Q + SZX;
static const long O_V   = O_K + SZX;
static const long O_SC  = O_V + SZX;
static const long O_RM  = O_SC + SZSC;            // 8*1024
static const long O_LG  = O_RM + 8192;
static const long O_NL  = O_LG + 64;
static const long O_FW  = O_NL + 64;
static const long O_FE  = O_FW + 16;
static const long ARENA_FLOATS = O_FE + 64;
__device__ __align__(16) float g_arena[ARENA_FLOATS];

// ---- fp16 arena ----
static const long H_LNQ = 0;
static const long H_LNK = H_LNQ + SZX;
static const long H_LNV = H_LNK + SZX;
static const long H_XN  = H_LNV + SZX;
static const long H_OB  = H_XN  + SZX;
static const long H_H   = H_OB  + SZX;            // 33.5M halves
static const long H_WQ  = H_H   + SZH;
static const long H_WK  = H_WQ  + (long)Dlay * DIMn * INNERn;
static const long H_WV  = H_WK  + (long)Dlay * DIMn * INNERn;
static const long H_WO  = H_WV  + (long)Dlay * DIMn * INNERn;
static const long H_W1  = H_WO  + (long)Dlay * INNERn * DIMn;
static const long H_W2  = H_W1  + (long)Dlay * En * DIMn * MLPn;
static const long ARENA_HALVES = H_W2 + (long)Dlay * En * MLPn * DIMn;
__device__ __align__(16) __half g_harena[ARENA_HALVES];

// ---------------- reductions ----------------
__device__ __forceinline__ float warpSum(float v) {
    #pragma unroll
    for (int o = 16; o; o >>= 1) v += __shfl_xor_sync(0xffffffffu, v, o);
    return v;
}
__device__ __forceinline__ float warpMax(float v) {
    #pragma unroll
    for (int o = 16; o; o >>= 1) v = fmaxf(v, __shfl_xor_sync(0xffffffffu, v, o));
    return v;
}

// ---------------- threefry2x32 (JAX-exact) ----------------
__device__ __forceinline__ void tf2x32(unsigned k0, unsigned k1, unsigned x0, unsigned x1,
                                       unsigned& o0, unsigned& o1) {
    unsigned ks[3] = {k0, k1, k0 ^ k1 ^ 0x1BD11BDAu};
    const int R0[4] = {13, 15, 26, 6};
    const int R1[4] = {17, 29, 16, 24};
    x0 += ks[0]; x1 += ks[1];
    #pragma unroll
    for (int i = 0; i < 5; i++) {
        #pragma unroll
        for (int r = 0; r < 4; r++) {
            int rot = (i & 1) ? R1[r] : R0[r];
            x0 += x1;
            x1 = (x1 << rot) | (x1 >> (32 - rot));
            x1 ^= x0;
        }
        x0 += ks[(i + 1) % 3];
        x1 += ks[(i + 2) % 3] + (unsigned)(i + 1);
    }
    o0 = x0; o1 = x1;
}

// ---------------- fp32 -> fp16 bulk convert ----------------
__global__ void f2h4(const float4* __restrict__ src, __half2* __restrict__ dst, long n4) {
    long i = (long)blockIdx.x * blockDim.x + threadIdx.x;
    if (i >= n4) return;
    float4 v = src[i];
    dst[2 * i]     = __floats2half2_rn(v.x, v.y);
    dst[2 * i + 1] = __floats2half2_rn(v.z, v.w);
}

// =================================================================
// fp16 WMMA GEMM: 128x128 CTA, BK=64, cp.async double-buffered,
// 8 warps (4Mx2N), warp 32x64, m16n16k16 fp32-accumulate.
// =================================================================
using HFragA = wmma::fragment<wmma::matrix_a, 16, 16, 16, __half, wmma::row_major>;
using HFragB = wmma::fragment<wmma::matrix_b, 16, 16, 16, __half, wmma::row_major>;
using HFragC = wmma::fragment<wmma::accumulator, 16, 16, 16, float>;

__device__ __forceinline__ void cpa16(void* dst_smem, const void* src) {
    unsigned d = (unsigned)__cvta_generic_to_shared(dst_smem);
    asm volatile("cp.async.cg.shared.global [%0], [%1], 16;\n" :: "r"(d), "l"(src));
}
__device__ __forceinline__ void cp_commit() { asm volatile("cp.async.commit_group;\n"); }
template <int N>
__device__ __forceinline__ void cp_wait() { asm volatile("cp.async.wait_group %0;\n" :: "n"(N)); }

#define HA_STR 72
#define HB_STR 136
#define HA_STAGE (128 * HA_STR)
#define HB_STAGE (64 * HB_STR)
static const int SMEMH_BYTES = (2 * HA_STAGE + 2 * HB_STAGE) * 2;  // 71680 B

__device__ __forceinline__ void hmm_cp(const __half* __restrict__ A, const __half* __restrict__ B,
                                       int lda, int ldb, int K, int m0, int n0,
                                       __half* sm, HFragC (&acc)[2][4]) {
    __half* sA[2] = { sm, sm + HA_STAGE };
    __half* sB[2] = { sm + 2 * HA_STAGE, sm + 2 * HA_STAGE + HB_STAGE };
    int tid = threadIdx.x;
    int warp = tid >> 5, wm = warp & 3, wn = warp >> 2;
    int arow = tid >> 1, acH = (tid & 1) * 32;    // 4 chunks of 8 halves
    int brow = tid >> 2, bcH = (tid & 3) * 32;
    const __half* Ab = A + (long)(m0 + arow) * lda + acH;
    const __half* Bb = B + (long)brow * ldb + n0 + bcH;
    __half* dA[2] = { sA[0] + arow * HA_STR + acH, sA[1] + arow * HA_STR + acH };
    __half* dB[2] = { sB[0] + brow * HB_STR + bcH, sB[1] + brow * HB_STR + bcH };

    int nIt = K >> 6;
    #pragma unroll
    for (int i = 0; i < 4; i++) cpa16(dA[0] + i * 8, Ab + i * 8);
    #pragma unroll
    for (int i = 0; i < 4; i++) cpa16(dB[0] + i * 8, Bb + i * 8);
    cp_commit();

    #pragma unroll 1
    for (int it = 0; it < nIt; it++) {
        int s = it & 1;
        if (it + 1 < nIt) {
            int s2 = s ^ 1;
            const __half* a = Ab + (it + 1) * 64;
            const __half* b = Bb + (long)(it + 1) * 64 * ldb;
            #pragma unroll
            for (int i = 0; i < 4; i++) cpa16(dA[s2] + i * 8, a + i * 8);
            #pragma unroll
            for (int i = 0; i < 4; i++) cpa16(dB[s2] + i * 8, b + i * 8);
            cp_commit();
            cp_wait<1>();
        } else {
            cp_wait<0>();
        }
        __syncthreads();
        #pragma unroll
        for (int kk = 0; kk < 4; kk++) {
            HFragA af[2];
            #pragma unroll
            for (int i = 0; i < 2; i++)
                wmma::load_matrix_sync(af[i], sA[s] + (wm * 32 + i * 16) * HA_STR + kk * 16, HA_STR);
            #pragma unroll
            for (int j = 0; j < 4; j++) {
                HFragB bf;
                wmma::load_matrix_sync(bf, sB[s] + (kk * 16) * HB_STR + wn * 64 + j * 16, HB_STR);
                wmma::mma_sync(acc[0][j], af[0], bf, acc[0][j]);
                wmma::mma_sync(acc[1][j], af[1], bf, acc[1][j]);
            }
        }
        __syncthreads();
    }
}

__device__ __forceinline__ void hacc_zero(HFragC (&acc)[2][4]) {
    #pragma unroll
    for (int i = 0; i < 2; i++)
        #pragma unroll
        for (int j = 0; j < 4; j++) wmma::fill_fragment(acc[i][j], 0.0f);
}

// EPI: 1 = fp32 C += acc + bias ; 2 = fp16 C = gelu(acc + bias) ; 3 = atomicAdd(fp32 C, (acc+bias)*w)
template <int EPI>
__device__ __forceinline__ void hepilogue(HFragC (&acc)[2][4], float* stage_w,
                                          void* __restrict__ Cv, const float* __restrict__ bias,
                                          int ldc, int m0, int n0, float w) {
    int tid = threadIdx.x, warp = tid >> 5, lane = tid & 31;
    int wm = warp & 3, wn = warp >> 2;
    int r = lane >> 1, cb = (lane & 1) * 8;
    #pragma unroll
    for (int i = 0; i < 2; i++)
        #pragma unroll
        for (int j = 0; j < 4; j++) {
            wmma::store_matrix_sync(stage_w, acc[i][j], 20, wmma::mem_row_major);
            __syncwarp();
            int row = m0 + wm * 32 + i * 16 + r;
            int col0 = n0 + wn * 64 + j * 16 + cb;
            #pragma unroll
            for (int c = 0; c < 8; c++) {
                float v = stage_w[r * 20 + cb + c];
                int col = col0 + c;
                long idx = (long)row * ldc + col;
                if (EPI == 1) {
                    float* C = (float*)Cv;
                    C[idx] = C[idx] + v + bias[col];
                } else if (EPI == 2) {
                    float u = v + bias[col];
                    ((__half*)Cv)[idx] = __float2half_rn(0.5f * u * (1.0f + erff(u * 0.70710678118654752f)));
                } else {
                    atomicAdd(&((float*)Cv)[idx], (v + bias[col]) * w);
                }
            }
            __syncwarp();
        }
}

// fused QKV (fp16 in, fp32 out)
__global__ __launch_bounds__(256, 2) void qkv_h(const __half* __restrict__ lnq, const __half* __restrict__ lnk,
                                                const __half* __restrict__ lnv,
                                                const __half* __restrict__ Wq, const __half* __restrict__ Wk,
                                                const __half* __restrict__ Wv,
                                                float* __restrict__ q, float* __restrict__ k,
                                                float* __restrict__ v) {
    extern __shared__ __half smh[];
    int z = blockIdx.z;
    const __half* A = (z == 0) ? lnq : (z == 1) ? lnk : lnv;
    const __half* B = (z == 0) ? Wq : (z == 1) ? Wk : Wv;
    float* C = (z == 0) ? q : (z == 1) ? k : v;
    int m0 = blockIdx.y * 128, n0 = blockIdx.x * 128;
    HFragC acc[2][4];
    hacc_zero(acc);
    hmm_cp(A, B, DIMn, INNERn, DIMn, m0, n0, smh, acc);
    int warp = threadIdx.x >> 5, wm = warp & 3, wn = warp >> 2;
    #pragma unroll
    for (int i = 0; i < 2; i++)
        #pragma unroll
        for (int j = 0; j < 4; j++)
            wmma::store_matrix_sync(&C[(long)(m0 + wm * 32 + i * 16) * INNERn + n0 + wn * 64 + j * 16],
                                    acc[i][j], INNERn, wmma::mem_row_major);
}

// X += ob @ Wo + bo
__global__ __launch_bounds__(256, 2) void wo_h(const __half* __restrict__ A, const __half* __restrict__ B,
                                               float* __restrict__ C, const float* __restrict__ bias) {
    extern __shared__ __half smh[];
    int m0 = blockIdx.y * 128, n0 = blockIdx.x * 128;
    HFragC acc[2][4];
    hacc_zero(acc);
    hmm_cp(A, B, INNERn, DIMn, INNERn, m0, n0, smh, acc);
    float* stage = (float*)smh + (threadIdx.x >> 5) * 320;
    hepilogue<1>(acc, stage, C, bias, DIMn, m0, n0, 0.0f);
}

// MoE 1: H16 = gelu(xn16 @ W1[e] + b1[e])
__global__ __launch_bounds__(256, 2) void moe1_h(const __half* __restrict__ xn, const __half* __restrict__ W1l,
                                                 const float* __restrict__ b1l, __half* __restrict__ H,
                                                 const int* __restrict__ fe, const float* __restrict__ fw) {
    extern __shared__ __half smh[];
    int n = blockIdx.z;
    if (fw[n] == 0.0f) return;
    int e = fe[n];
    const __half* A = xn + (long)(n >> 1) * Ssz * DIMn;
    const __half* B = W1l + (long)e * DIMn * MLPn;
    __half* C = H + (long)n * Ssz * MLPn;
    const float* bias = b1l + (long)e * MLPn;
    int m0 = blockIdx.y * 128, n0 = blockIdx.x * 128;
    HFragC acc[2][4];
    hacc_zero(acc);
    hmm_cp(A, B, DIMn, MLPn, DIMn, m0, n0, smh, acc);
    float* stage = (float*)smh + (threadIdx.x >> 5) * 320;
    hepilogue<2>(acc, stage, C, bias, MLPn, m0, n0, 0.0f);
}

// MoE 2: X[slot>>1] += (H16 @ W2[e] + b2[e]) * w
__global__ __launch_bounds__(256, 2) void moe2_h(const __half* __restrict__ H, const __half* __restrict__ W2l,
                                                 const float* __restrict__ b2l, float* __restrict__ X,
                                                 const int* __restrict__ fe, const float* __restrict__ fw) {
    extern __shared__ __half smh[];
    int n = blockIdx.z;
    float w = fw[n];
    if (w == 0.0f) return;
    int e = fe[n];
    const __half* A = H + (long)n * Ssz * MLPn;
    const __half* B = W2l + (long)e * MLPn * DIMn;
    float* C = X + (long)(n >> 1) * Ssz * DIMn;
    const float* bias = b2l + (long)e * DIMn;
    int m0 = blockIdx.y * 128, n0 = blockIdx.x * 128;
    HFragC acc[2][4];
    hacc_zero(acc);
    hmm_cp(A, B, MLPn, DIMn, MLPn, m0, n0, smh, acc);
    float* stage = (float*)smh + (threadIdx.x >> 5) * 320;
    hepilogue<3>(acc, stage, C, bias, DIMn, m0, n0, w);
}

// ---------------- FFMA GEMM (attention): 64x64x16 tile ----------------
template <bool TB>
__device__ __forceinline__ void mm_body(const float* __restrict__ A, const float* __restrict__ B,
                                        int lda, int ldb, int K, int m0, int n0,
                                        float (&acc)[4][4], float (*As)[64], float (*Bs)[64]) {
    int tid = threadIdx.x;
    int ar = tid >> 2;
    int ac = (tid & 3) << 2;
    int ty4 = (tid >> 4) << 2;
    int tx4 = (tid & 15) << 2;
    for (int k0 = 0; k0 < K; k0 += 16) {
        float4 a4 = *(const float4*)(A + (long)(m0 + ar) * lda + k0 + ac);
        As[ac + 0][ar] = a4.x; As[ac + 1][ar] = a4.y;
        As[ac + 2][ar] = a4.z; As[ac + 3][ar] = a4.w;
        if (TB) {
            float4 b4 = *(const float4*)(B + (long)(n0 + ar) * ldb + k0 + ac);
            Bs[ac + 0][ar] = b4.x; Bs[ac + 1][ar] = b4.y;
            Bs[ac + 2][ar] = b4.z; Bs[ac + 3][ar] = b4.w;
        } else {
            int rb = tid >> 4;
            int cb = (tid & 15) << 2;
            *(float4*)&Bs[rb][cb] = *(const float4*)(B + (long)(k0 + rb) * ldb + n0 + cb);
        }
        __syncthreads();
        #pragma unroll
        for (int kk = 0; kk < 16; kk++) {
            float4 av = *(const float4*)&As[kk][ty4];
            float4 bv = *(const float4*)&Bs[kk][tx4];
            float a0[4] = {av.x, av.y, av.z, av.w};
            float b0[4] = {bv.x, bv.y, bv.z, bv.w};
            #pragma unroll
            for (int i = 0; i < 4; i++)
                #pragma unroll
                for (int j = 0; j < 4; j++)
                    acc[i][j] += a0[i] * b0[j];
        }
        __syncthreads();
    }
}

// HOUT: write fp16 C (for PV output)
template <bool TB, bool HOUT>
__global__ __launch_bounds__(256) void gemm_k(const float* __restrict__ Ag, const float* __restrict__ Bg,
                                              void* __restrict__ Cgv,
                                              int K, int lda, int ldb, int ldc,
                                              long sAb, long sAh, long sBb, long sBh,
                                              long sCb, long sCh, int HH, float scale) {
    __shared__ __align__(16) float As[16][64];
    __shared__ __align__(16) float Bs[16][64];
    int z = blockIdx.z;
    int zb = z / HH, zh = z - zb * HH;
    const float* A = Ag + zb * sAb + zh * sAh;
    const float* B = Bg + zb * sBb + zh * sBh;
    int m0 = blockIdx.y * 64, n0 = blockIdx.x * 64;
    float acc[4][4] = {};
    mm_body<TB>(A, B, lda, ldb, K, m0, n0, acc, As, Bs);
    int ty4 = (threadIdx.x >> 4) << 2;
    int tx4 = (threadIdx.x & 15) << 2;
    #pragma unroll
    for (int i = 0; i < 4; i++)
        #pragma unroll
        for (int j = 0; j < 4; j++) {
            long idx = (long)(m0 + ty4 + i) * ldc + n0 + tx4 + j;
            if (HOUT) ((__half*)Cgv)[zb * sCb + zh * sCh + idx] = __float2half_rn(acc[i][j] * scale);
            else      ((float*)Cgv)[zb * sCb + zh * sCh + idx] = acc[i][j] * scale;
        }
}

// ---------------- LayerNorm (fp16 outputs) ----------------
__global__ __launch_bounds__(256) void ln3_k(const float* __restrict__ X,
                                             const float* __restrict__ wq, const float* __restrict__ bq,
                                             const float* __restrict__ wk, const float* __restrict__ bk,
                                             const float* __restrict__ wv, const float* __restrict__ bv,
                                             __half* __restrict__ oq, __half* __restrict__ ok,
                                             __half* __restrict__ ov) {
    __shared__ float sh[8];
    long row = blockIdx.x;
    const float* xr = X + row * DIMn;
    int t = threadIdx.x;
    float v[4]; float s = 0.f;
    #pragma unroll
    for (int i = 0; i < 4; i++) { v[i] = xr[t + i * 256]; s += v[i]; }
    s = warpSum(s);
    if ((t & 31) == 0) sh[t >> 5] = s;
    __syncthreads();
    if (t < 32) { float a = (t < 8) ? sh[t] : 0.f; a = warpSum(a); if (t == 0) sh[0] = a; }
    __syncthreads();
    float mean = sh[0] * (1.0f / DIMn);
    __syncthreads();
    float ss = 0.f;
    #pragma unroll
    for (int i = 0; i < 4; i++) { float d = v[i] - mean; ss += d * d; }
    ss = warpSum(ss);
    if ((t & 31) == 0) sh[t >> 5] = ss;
    __syncthreads();
    if (t < 32) { float a = (t < 8) ? sh[t] : 0.f; a = warpSum(a); if (t == 0) sh[0] = a; }
    __syncthreads();
    float rstd = rsqrtf(sh[0] * (1.0f / DIMn) + 1e-5f);
    #pragma unroll
    for (int i = 0; i < 4; i++) {
        int c = t + i * 256;
        float xh = (v[i] - mean) * rstd;
        long idx = row * DIMn + c;
        oq[idx] = __float2half_rn(xh * wq[c] + bq[c]);
        ok[idx] = __float2half_rn(xh * wk[c] + bk[c]);
        ov[idx] = __float2half_rn(xh * wv[c] + bv[c]);
    }
}

__global__ __launch_bounds__(256) void ln1_k(const float* __restrict__ X,
                                             const float* __restrict__ w, const float* __restrict__ b,
                                             __half* __restrict__ out) {
    __shared__ float sh[8];
    long row = blockIdx.x;
    const float* xr = X + row * DIMn;
    int t = threadIdx.x;
    float v[4]; float s = 0.f;
    #pragma unroll
    for (int i = 0; i < 4; i++) { v[i] = xr[t + i * 256]; s += v[i]; }
    s = warpSum(s);
    if ((t & 31) == 0) sh[t >> 5] = s;
    __syncthreads();
    if (t < 32) { float a = (t < 8) ? sh[t] : 0.f; a = warpSum(a); if (t == 0) sh[0] = a; }
    __syncthreads();
    float mean = sh[0] * (1.0f / DIMn);
    __syncthreads();
    float ss = 0.f;
    #pragma unroll
    for (int i = 0; i < 4; i++) { float d = v[i] - mean; ss += d * d; }
    ss = warpSum(ss);
    if ((t & 31) == 0) sh[t >> 5] = ss;
    __syncthreads();
    if (t < 32) { float a = (t < 8) ? sh[t] : 0.f; a = warpSum(a); if (t == 0) sh[0] = a; }
    __syncthreads();
    float rstd = rsqrtf(sh[0] * (1.0f / DIMn) + 1e-5f);
    #pragma unroll
    for (int i = 0; i < 4; i++) {
        int c = t + i * 256;
        long idx = row * DIMn + c;
        out[idx] = __float2half_rn((v[i] - mean) * rstd * w[c] + b[c]);
    }
}

// ---------------- softmax over rows of 512 ----------------
__global__ __launch_bounds__(128) void softmax_k(float* __restrict__ S) {
    __shared__ float sh[4];
    long row = blockIdx.x;
    float* p = S + row * 512;
    int t = threadIdx.x;
    float v[4];
    #pragma unroll
    for (int i = 0; i < 4; i++) v[i] = p[t + i * 128];
    float m = fmaxf(fmaxf(v[0], v[1]), fmaxf(v[2], v[3]));
    m = warpMax(m);
    if ((t & 31) == 0) sh[t >> 5] = m;
    __syncthreads();
    if (t < 32) { float a = (t < 4) ? sh[t] : -INFINITY; a = warpMax(a); if (t == 0) sh[0] = a; }
    __syncthreads();
    m = sh[0];
    __syncthreads();
    float s = 0.f;
    #pragma unroll
    for (int i = 0; i < 4; i++) { v[i] = expf(v[i] - m); s += v[i]; }
    s = warpSum(s);
    if ((t & 31) == 0) sh[t >> 5] = s;
    __syncthreads();
    if (t < 32) { float a = (t < 4) ? sh[t] : 0.f; a = warpSum(a); if (t == 0) sh[0] = a; }
    __syncthreads();
    float inv = 1.0f / sh[0];
    #pragma unroll
    for (int i = 0; i < 4; i++) p[t + i * 128] = v[i] * inv;
}

// ---------------- router mean over LR ----------------
__global__ void rimean_k(const float* __restrict__ ri, float* __restrict__ rm) {
    int i = blockIdx.x * 256 + threadIdx.x;   // 8192 total
    int b = i >> 10, d = i & 1023;
    float s = 0.f;
    for (int r = 0; r < LRn; r++) s += ri[((long)b * LRn + r) * DIMn + d];
    rm[i] = s * (1.0f / LRn);
}

// ---------------- router logits ----------------
__global__ __launch_bounds__(256) void logits_k(const float* __restrict__ rm,
                                                const float* __restrict__ Wr, const float* __restrict__ br,
                                                const float* __restrict__ Wn, const float* __restrict__ bn,
                                                float* __restrict__ lg, float* __restrict__ nl) {
    __shared__ float sh[16];
    int b = blockIdx.x >> 3, e = blockIdx.x & 7;
    int t = threadIdx.x;
    float s1 = 0.f, s2 = 0.f;
    for (int d = t; d < DIMn; d += 256) {
        float r = rm[b * DIMn + d];
        s1 += r * Wr[(long)d * En + e];
        s2 += r * Wn[(long)d * En + e];
    }
    s1 = warpSum(s1); s2 = warpSum(s2);
    if ((t & 31) == 0) { sh[t >> 5] = s1; sh[8 + (t >> 5)] = s2; }
    __syncthreads();
    if (t == 0) {
        float a = 0.f, c = 0.f;
        for (int i = 0; i < 8; i++) { a += sh[i]; c += sh[8 + i]; }
        lg[blockIdx.x] = a + br[e];
        nl[blockIdx.x] = c + bn[e];
    }
}

// ---------------- noisy top-k routing + capacity ----------------
__global__ void route_k(const float* __restrict__ logits, const float* __restrict__ nlog, int l,
                        int* __restrict__ fe, float* __restrict__ fw) {
    __shared__ float sc[64];
    __shared__ int se[16];
    __shared__ float sg[16];
    int t = threadIdx.x;
    if (t < 64) {
        unsigned kk0, kk1;
        tf2x32(0u, 42u, 0u, (unsigned)l, kk0, kk1);       // fold_in(key(42), l)
        unsigned o0, o1;
        tf2x32(kk0, kk1, 0u, (unsigned)t, o0, o1);        // partitionable counter mode
        unsigned bits = o0 ^ o1;
        float f = __uint_as_float(0x3f800000u | (bits >> 9)) - 1.0f;
        const float lo = -0.99999994f;
        float u = f * 2.0f + lo;
        u = fmaxf(lo, u);
        float g = 1.41421356237309515f * erfinvf(u);
        float xnl = nlog[t];
        float sp = fmaxf(xnl, 0.f) + log1pf(expf(-fabsf(xnl)));
        sc[t] = logits[t] + g * sp;
    }
    __syncthreads();
    if (t < 8) {
        const float* row = sc + t * 8;
        int e0 = 0; float v0 = row[0];
        for (int e = 1; e < 8; e++) if (row[e] > v0) { v0 = row[e]; e0 = e; }
        int e1 = -1; float v1 = -INFINITY;
        for (int e = 0; e < 8; e++) if (e != e0 && row[e] > v1) { v1 = row[e]; e1 = e; }
        float d = expf(v1 - v0);
        float inv = 1.0f / (1.0f + d);
        se[t * 2] = e0; se[t * 2 + 1] = e1;
        sg[t * 2] = inv; sg[t * 2 + 1] = d * inv;
    }
    __syncthreads();
    if (t == 0) {
        int cnt[8] = {0, 0, 0, 0, 0, 0, 0, 0};
        for (int n = 0; n < 16; n++) {
            int e = se[n];
            float w = (cnt[e] < CAPn) ? sg[n] : 0.0f;
            cnt[e]++;
            fe[n] = e; fw[n] = w;
        }
    }
}

// ---------------- host launch ----------------
static void conv_w(const float* src, __half* dst, long n) {
    long n4 = n / 4;
    int blocks = (int)((n4 + 255) / 256);
    f2h4<<<blocks, 256>>>((const float4*)src, (__half2*)dst, n4);
}

extern "C" void kernel_launch(void* const* d_in, const int* in_sizes, int n_in,
                              void* d_out, int out_size) {
    (void)in_sizes; (void)n_in; (void)out_size;
    const float* router_input = (const float*)d_in[0];
    const float* x0   = (const float*)d_in[1];
    const float* nq_w = (const float*)d_in[2];
    const float* nq_b = (const float*)d_in[3];
    const float* nk_w = (const float*)d_in[4];
    const float* nk_b = (const float*)d_in[5];
    const float* nv_w = (const float*)d_in[6];
    const float* nv_b = (const float*)d_in[7];
    const float* Wq   = (const float*)d_in[8];
    const float* Wk   = (const float*)d_in[9];
    const float* Wv   = (const float*)d_in[10];
    const float* Wo   = (const float*)d_in[11];
    const float* bo   = (const float*)d_in[12];
    const float* nm_w = (const float*)d_in[13];
    const float* nm_b = (const float*)d_in[14];
    const float* Wr   = (const float*)d_in[15];
    const float* br   = (const float*)d_in[16];
    const float* Wn   = (const float*)d_in[17];
    const float* bn   = (const float*)d_in[18];
    const float* W1   = (const float*)d_in[19];
    const float* b1   = (const float*)d_in[20];
    const float* W2   = (const float*)d_in[21];
    const float* b2   = (const float*)d_in[22];

    float* X = (float*)d_out;
    float* arena = nullptr;
    cudaGetSymbolAddress((void**)&arena, g_arena);
    __half* ha = nullptr;
    cudaGetSymbolAddress((void**)&ha, g_harena);

    float* qb  = arena + O_Q;
    float* kb  = arena + O_K;
    float* vb  = arena + O_V;
    float* sc  = arena + O_SC;
    float* rm  = arena + O_RM;
    float* lg  = arena + O_LG;
    float* nl  = arena + O_NL;
    float* fw  = arena + O_FW;
    int*   fe  = (int*)(arena + O_FE);

    __half* lnq = ha + H_LNQ;
    __half* lnk = ha + H_LNK;
    __half* lnv = ha + H_LNV;
    __half* xnh = ha + H_XN;
    __half* obh = ha + H_OB;
    __half* hbh = ha + H_H;
    __half* Wq16 = ha + H_WQ;
    __half* Wk16 = ha + H_WK;
    __half* Wv16 = ha + H_WV;
    __half* Wo16 = ha + H_WO;
    __half* W116 = ha + H_W1;
    __half* W216 = ha + H_W2;

    cudaFuncSetAttribute(qkv_h, cudaFuncAttributeMaxDynamicSharedMemorySize, SMEMH_BYTES);
    cudaFuncSetAttribute(wo_h, cudaFuncAttributeMaxDynamicSharedMemorySize, SMEMH_BYTES);
    cudaFuncSetAttribute(moe1_h, cudaFuncAttributeMaxDynamicSharedMemorySize, SMEMH_BYTES);
    cudaFuncSetAttribute(moe2_h, cudaFuncAttributeMaxDynamicSharedMemorySize, SMEMH_BYTES);

    // weight conversion (once per call; all layers)
    conv_w(Wq, Wq16, (long)Dlay * DIMn * INNERn);
    conv_w(Wk, Wk16, (long)Dlay * DIMn * INNERn);
    conv_w(Wv, Wv16, (long)Dlay * DIMn * INNERn);
    conv_w(Wo, Wo16, (long)Dlay * INNERn * DIMn);
    conv_w(W1, W116, (long)Dlay * En * DIMn * MLPn);
    conv_w(W2, W216, (long)Dlay * En * MLPn * DIMn);

    cudaMemcpyAsync(X, x0, sizeof(float) * SZX, cudaMemcpyDeviceToDevice);
    rimean_k<<<32, 256>>>(router_input, rm);

    const long sQb = (long)Ssz * INNERn;
    const long sQh = DHn;
    const long sScb = (long)Hn * Ssz * Ssz;
    const long sSch = (long)Ssz * Ssz;

    for (int l = 0; l < Dlay; l++) {
        ln3_k<<<Bn * Ssz, 256>>>(X, nq_w + l * DIMn, nq_b + l * DIMn,
                                 nk_w + l * DIMn, nk_b + l * DIMn,
                                 nv_w + l * DIMn, nv_b + l * DIMn, lnq, lnk, lnv);

        qkv_h<<<dim3(INNERn / 128, Bn * Ssz / 128, 3), 256, SMEMH_BYTES>>>(
            lnq, lnk, lnv,
            Wq16 + (long)l * DIMn * INNERn, Wk16 + (long)l * DIMn * INNERn,
            Wv16 + (long)l * DIMn * INNERn, qb, kb, vb);

        // scores = Q K^T * scale
        gemm_k<true, false><<<dim3(Ssz / 64, Ssz / 64, Bn * Hn), 256>>>(
            qb, kb, sc, DHn, INNERn, INNERn, Ssz,
            sQb, sQh, sQb, sQh, sScb, sSch, Hn, 0.125f);

        softmax_k<<<Bn * Hn * Ssz, 128>>>(sc);

        // ob16 = P V (fp16 out)
        gemm_k<false, true><<<dim3(1, Ssz / 64, Bn * Hn), 256>>>(
            sc, vb, obh, Ssz, Ssz, INNERn, INNERn,
            sScb, sSch, sQb, sQh, sQb, sQh, Hn, 1.0f);

        // X += ob @ Wo + bo
        wo_h<<<dim3(DIMn / 128, Bn * Ssz / 128), 256, SMEMH_BYTES>>>(
            obh, Wo16 + (long)l * INNERn * DIMn, X, bo + l * DIMn);

        logits_k<<<Bn * En, 256>>>(rm, Wr + (long)l * DIMn * En, br + l * En,
                                   Wn + (long)l * DIMn * En, bn + l * En, lg, nl);
        route_k<<<1, 64>>>(lg, nl, l, fe, fw);

        ln1_k<<<Bn * Ssz, 256>>>(X, nm_w + l * DIMn, nm_b + l * DIMn, xnh);
        moe1_h<<<dim3(MLPn / 128, Ssz / 128, Bn * Kn), 256, SMEMH_BYTES>>>(
            xnh, W116 + (long)l * En * DIMn * MLPn, b1 + (long)l * En * MLPn, hbh, fe, fw);
        moe2_h<<<dim3(DIMn / 128, Ssz / 128, Bn * Kn), 256, SMEMH_BYTES>>>(
            hbh, W216 + (long)l * En * MLPn * DIMn, b2 + (long)l * En * DIMn, X, fe, fw);
    }
}